// round 3
// baseline (speedup 1.0000x reference)
#include <cuda_runtime.h>
#include <cuda_bf16.h>
#include <cstdint>

#define BB 2
#define SS 2048
#define EE 1024
#define HH 16
#define DD 64
#define MM (BB*SS)
#define PAD 68
#define BK 32              // k-chunk in bf16 elems
#define ASTRIDE 40         // smem row stride (halves): 80B, conflict-free ldmatrix

// ---------------- scratch (device globals: allocation-free rule) ------------
__device__ float g_Q[BB*HH*SS*DD];
__device__ float g_K[BB*HH*SS*DD];
__device__ float g_V[BB*HH*SS*DD];
__device__ float g_att[MM*EE];
__device__ __nv_bfloat16 g_xh[MM*EE],  g_xl[MM*EE];
__device__ __nv_bfloat16 g_ah[MM*EE],  g_al[MM*EE];
__device__ __nv_bfloat16 g_wqh[EE*EE], g_wql[EE*EE];
__device__ __nv_bfloat16 g_wkh[EE*EE], g_wkl[EE*EE];
__device__ __nv_bfloat16 g_wvh[EE*EE], g_wvl[EE*EE];
__device__ __nv_bfloat16 g_woh[EE*EE], g_wol[EE*EE];

// ---------------- warp-level MMA helpers (compute_103-safe) -----------------
__device__ __forceinline__ uint32_t smem_u32(const void* p) {
    uint32_t a;
    asm("{ .reg .u64 t; cvta.to.shared.u64 t, %1; cvt.u32.u64 %0, t; }" : "=r"(a) : "l"(p));
    return a;
}
__device__ __forceinline__ void ldsm_x4(uint32_t& r0, uint32_t& r1, uint32_t& r2,
                                        uint32_t& r3, uint32_t addr) {
    asm volatile("ldmatrix.sync.aligned.m8n8.x4.shared.b16 {%0,%1,%2,%3}, [%4];"
                 : "=r"(r0), "=r"(r1), "=r"(r2), "=r"(r3) : "r"(addr));
}
__device__ __forceinline__ void ldsm_x2(uint32_t& r0, uint32_t& r1, uint32_t addr) {
    asm volatile("ldmatrix.sync.aligned.m8n8.x2.shared.b16 {%0,%1}, [%2];"
                 : "=r"(r0), "=r"(r1) : "r"(addr));
}
__device__ __forceinline__ void mma_bf16(float* c, const uint32_t* a, const uint32_t* b) {
    asm volatile(
        "mma.sync.aligned.m16n8k16.row.col.f32.bf16.bf16.f32 "
        "{%0,%1,%2,%3}, {%4,%5,%6,%7}, {%8,%9}, {%0,%1,%2,%3};"
        : "+f"(c[0]), "+f"(c[1]), "+f"(c[2]), "+f"(c[3])
        : "r"(a[0]), "r"(a[1]), "r"(a[2]), "r"(a[3]), "r"(b[0]), "r"(b[1]));
}

// ---------------- fp32 -> (hi, lo) bf16 split conversion --------------------
__global__ __launch_bounds__(256) void convert_hl(
    const float* __restrict__ in, __nv_bfloat16* __restrict__ hi,
    __nv_bfloat16* __restrict__ lo, int n4)
{
    int i = blockIdx.x * blockDim.x + threadIdx.x;
    if (i >= n4) return;
    float4 v = ((const float4*)in)[i];
    float vv[4] = {v.x, v.y, v.z, v.w};
    __nv_bfloat16 h[4], l[4];
#pragma unroll
    for (int k = 0; k < 4; k++) {
        h[k] = __float2bfloat16(vv[k]);
        l[k] = __float2bfloat16(vv[k] - __bfloat162float(h[k]));
    }
    ((__nv_bfloat162*)hi)[2*i+0] = __nv_bfloat162(h[0], h[1]);
    ((__nv_bfloat162*)hi)[2*i+1] = __nv_bfloat162(h[2], h[3]);
    ((__nv_bfloat162*)lo)[2*i+0] = __nv_bfloat162(l[0], l[1]);
    ((__nv_bfloat162*)lo)[2*i+1] = __nv_bfloat162(l[2], l[3]);
}

// ---------------------------------------------------------------------------
// mma.sync split-bf16 GEMM: C[m,n] = sum_k A[m,k]*W[n,k] + bias[n]
// A,W given as (hi, lo) bf16 pairs. 128x128 CTA tile, BK=32, 8 warps (64x32
// warp tiles), 3 MMAs per (m,n,k16) for split precision (~2^-17 effective).
// sel: 0/1/2 -> scatter into g_Q/g_K/g_V [B,H,S,D];  -1 -> row-major Cout.
// ---------------------------------------------------------------------------
__global__ __launch_bounds__(256) void gemm_mma(
    const __nv_bfloat16* __restrict__ Ah, const __nv_bfloat16* __restrict__ Al,
    const __nv_bfloat16* __restrict__ Bh, const __nv_bfloat16* __restrict__ Bl,
    const float* __restrict__ bias, float* __restrict__ Cout, int sel)
{
    __shared__ __nv_bfloat16 sAh[128*ASTRIDE], sAl[128*ASTRIDE];
    __shared__ __nv_bfloat16 sBh[128*ASTRIDE], sBl[128*ASTRIDE];

    const int t    = threadIdx.x;
    const int warp = t >> 5;
    const int lane = t & 31;
    const int row0 = blockIdx.x * 128;
    const int col0 = blockIdx.y * 128;
    const int wm   = (warp >> 2) * 64;     // warp row offset (0 or 64)
    const int wn   = (warp & 3) * 32;      // warp col offset

    float acc[4][4][4];
#pragma unroll
    for (int mi = 0; mi < 4; mi++)
#pragma unroll
        for (int ni = 0; ni < 4; ni++)
#pragma unroll
            for (int k = 0; k < 4; k++) acc[mi][ni][k] = 0.f;

    // loader mapping: thread -> (row, 16-elem half)
    const int lr = t >> 1;                 // 0..127
    const int lh = (t & 1) * 16;           // 0 or 16

    // ldmatrix address components
    const int a_row  = lane & 15;          // 0..15
    const int a_half = (lane >> 4) * 8;    // 0 or 8 (k offset)
    const int b_row  = lane & 7;           // n within frag
    const int b_half = ((lane >> 3) & 1) * 8;  // k offset (lanes 0..15 matter)

    const uint32_t uAh = smem_u32(sAh), uAl = smem_u32(sAl);
    const uint32_t uBh = smem_u32(sBh), uBl = smem_u32(sBl);

    for (int k0 = 0; k0 < EE; k0 += BK) {
        // ---- stage tiles: 128 rows x 32 halves each, 4 arrays ----
        {
            const __nv_bfloat16* gA = Ah + (size_t)(row0 + lr) * EE + k0 + lh;
            const __nv_bfloat16* gL = Al + (size_t)(row0 + lr) * EE + k0 + lh;
            const __nv_bfloat16* gB = Bh + (size_t)(col0 + lr) * EE + k0 + lh;
            const __nv_bfloat16* gM = Bl + (size_t)(col0 + lr) * EE + k0 + lh;
            uint4 a0 = ((const uint4*)gA)[0], a1 = ((const uint4*)gA)[1];
            uint4 l0 = ((const uint4*)gL)[0], l1 = ((const uint4*)gL)[1];
            uint4 b0 = ((const uint4*)gB)[0], b1 = ((const uint4*)gB)[1];
            uint4 m0 = ((const uint4*)gM)[0], m1 = ((const uint4*)gM)[1];
            uint4* dA = (uint4*)&sAh[lr*ASTRIDE + lh];
            uint4* dL = (uint4*)&sAl[lr*ASTRIDE + lh];
            uint4* dB = (uint4*)&sBh[lr*ASTRIDE + lh];
            uint4* dM = (uint4*)&sBl[lr*ASTRIDE + lh];
            dA[0] = a0; dA[1] = a1;
            dL[0] = l0; dL[1] = l1;
            dB[0] = b0; dB[1] = b1;
            dM[0] = m0; dM[1] = m1;
        }
        __syncthreads();

#pragma unroll
        for (int ks = 0; ks < BK/16; ks++) {
            const int kk = ks * 16;
            // B fragments (hi & lo) for 4 n-frags
            uint32_t bH[4][2], bL[4][2];
#pragma unroll
            for (int ni = 0; ni < 4; ni++) {
                uint32_t boff = (uint32_t)((wn + ni*8 + b_row) * ASTRIDE + kk + b_half) * 2;
                ldsm_x2(bH[ni][0], bH[ni][1], uBh + boff);
                ldsm_x2(bL[ni][0], bL[ni][1], uBl + boff);
            }
#pragma unroll
            for (int mi = 0; mi < 4; mi++) {
                uint32_t aoff = (uint32_t)((wm + mi*16 + a_row) * ASTRIDE + kk + a_half) * 2;
                uint32_t aH[4], aL[4];
                ldsm_x4(aH[0], aH[1], aH[2], aH[3], uAh + aoff);
                ldsm_x4(aL[0], aL[1], aL[2], aL[3], uAl + aoff);
#pragma unroll
                for (int ni = 0; ni < 4; ni++) {
                    mma_bf16(acc[mi][ni], aH, bH[ni]);
                    mma_bf16(acc[mi][ni], aH, bL[ni]);
                    mma_bf16(acc[mi][ni], aL, bH[ni]);
                }
            }
        }
        __syncthreads();
    }

    // ---- epilogue: c fragment -> global, add bias ----
    const int gr = lane >> 2;              // 0..7
    const int gc = (lane & 3) * 2;         // 0,2,4,6
#pragma unroll
    for (int mi = 0; mi < 4; mi++) {
#pragma unroll
        for (int ni = 0; ni < 4; ni++) {
#pragma unroll
            for (int half = 0; half < 2; half++) {
                const int r = wm + mi*16 + gr + half*8;
                const int c = wn + ni*8 + gc;
                const int m = row0 + r;
                const int n = col0 + c;
                float v0 = acc[mi][ni][half*2+0] + bias[n];
                float v1 = acc[mi][ni][half*2+1] + bias[n+1];
                if (sel < 0) {
                    *(float2*)&Cout[(size_t)m * EE + n] = make_float2(v0, v1);
                } else {
                    float* outp = (sel == 0) ? g_Q : (sel == 1) ? g_K : g_V;
                    const int b = m >> 11, s = m & 2047;
                    const int h = n >> 6,  d = n & 63;
                    *(float2*)&outp[(((size_t)b*HH + h)*SS + s)*DD + d] =
                        make_float2(v0, v1);
                }
            }
        }
    }
}

// ---------------------------------------------------------------------------
// Flash attention (fp32, online softmax) — unchanged (passing, at fp32 roofline)
// ---------------------------------------------------------------------------
__global__ __launch_bounds__(256) void attn_kernel()
{
    extern __shared__ float sm[];
    float* Qs = sm;
    float* Ks = Qs + 64*PAD;
    float* Vs = Ks + 64*PAD;
    float* Ps = Vs + 64*PAD;

    const int bh = blockIdx.y;
    const int qb = blockIdx.x;
    const int t  = threadIdx.x;
    const int tx = t & 15;
    const int ty = t >> 4;

    const float scale = 0.125f;
    const float* Qg = g_Q + ((size_t)bh*SS + qb*64)*DD;

    for (int idx = t; idx < 64*16; idx += 256) {
        int r = idx >> 4;
        int c = (idx & 15) * 4;
        float4 v = *(const float4*)(Qg + r*DD + c);
        v.x *= scale; v.y *= scale; v.z *= scale; v.w *= scale;
        *(float4*)&Qs[r*PAD + c] = v;
    }

    float m_i[4], l_i[4], o[4][4];
#pragma unroll
    for (int i = 0; i < 4; i++) {
        m_i[i] = -1e30f; l_i[i] = 0.f;
#pragma unroll
        for (int j = 0; j < 4; j++) o[i][j] = 0.f;
    }
    __syncthreads();

    for (int kb = 0; kb < SS/64; kb++) {
        const float* Kg = g_K + ((size_t)bh*SS + kb*64)*DD;
        const float* Vg = g_V + ((size_t)bh*SS + kb*64)*DD;
        for (int idx = t; idx < 64*16; idx += 256) {
            int r = idx >> 4;
            int c = (idx & 15) * 4;
            *(float4*)&Ks[r*PAD + c] = *(const float4*)(Kg + r*DD + c);
            *(float4*)&Vs[r*PAD + c] = *(const float4*)(Vg + r*DD + c);
        }
        __syncthreads();

        float s[4][4];
#pragma unroll
        for (int i = 0; i < 4; i++)
#pragma unroll
            for (int j = 0; j < 4; j++) s[i][j] = 0.f;

#pragma unroll
        for (int k = 0; k < DD; k += 4) {
            float4 q[4], kk[4];
#pragma unroll
            for (int i = 0; i < 4; i++) q[i]  = *(const float4*)&Qs[(ty*4+i)*PAD + k];
#pragma unroll
            for (int j = 0; j < 4; j++) kk[j] = *(const float4*)&Ks[(tx*4+j)*PAD + k];
#pragma unroll
            for (int i = 0; i < 4; i++)
#pragma unroll
                for (int j = 0; j < 4; j++)
                    s[i][j] += q[i].x*kk[j].x + q[i].y*kk[j].y
                             + q[i].z*kk[j].z + q[i].w*kk[j].w;
        }

#pragma unroll
        for (int i = 0; i < 4; i++) {
            float rm = fmaxf(fmaxf(s[i][0], s[i][1]), fmaxf(s[i][2], s[i][3]));
#pragma unroll
            for (int off = 8; off >= 1; off >>= 1)
                rm = fmaxf(rm, __shfl_xor_sync(0xffffffffu, rm, off));
            float mnew = fmaxf(m_i[i], rm);

            float sum = 0.f;
#pragma unroll
            for (int j = 0; j < 4; j++) { s[i][j] = __expf(s[i][j] - mnew); sum += s[i][j]; }
#pragma unroll
            for (int off = 8; off >= 1; off >>= 1)
                sum += __shfl_xor_sync(0xffffffffu, sum, off);

            float alpha = __expf(m_i[i] - mnew);
            l_i[i] = l_i[i]*alpha + sum;
            m_i[i] = mnew;
#pragma unroll
            for (int j = 0; j < 4; j++) {
                o[i][j] *= alpha;
                Ps[(ty*4+i)*PAD + tx*4+j] = s[i][j];
            }
        }
        __syncthreads();

#pragma unroll
        for (int c0 = 0; c0 < 64; c0 += 4) {
            float4 p[4];
#pragma unroll
            for (int i = 0; i < 4; i++) p[i] = *(const float4*)&Ps[(ty*4+i)*PAD + c0];
#pragma unroll
            for (int cc = 0; cc < 4; cc++) {
                float4 v = *(const float4*)&Vs[(c0+cc)*PAD + tx*4];
#pragma unroll
                for (int i = 0; i < 4; i++) {
                    float pv = (cc == 0) ? p[i].x : (cc == 1) ? p[i].y
                             : (cc == 2) ? p[i].z : p[i].w;
                    o[i][0] += pv * v.x;
                    o[i][1] += pv * v.y;
                    o[i][2] += pv * v.z;
                    o[i][3] += pv * v.w;
                }
            }
        }
        __syncthreads();
    }

    const int b = bh >> 4;
    const int h = bh & 15;
#pragma unroll
    for (int i = 0; i < 4; i++) {
        float inv = 1.f / l_i[i];
        int srow = qb*64 + ty*4 + i;
        float4 v = make_float4(o[i][0]*inv, o[i][1]*inv, o[i][2]*inv, o[i][3]*inv);
        *(float4*)&g_att[((size_t)b*SS + srow)*EE + h*DD + tx*4] = v;
    }
}

// ---------------------------------------------------------------------------
extern "C" void kernel_launch(void* const* d_in, const int* in_sizes, int n_in,
                              void* d_out, int out_size)
{
    const float* x  = (const float*)d_in[0];
    const float* Wq = (const float*)d_in[1];
    const float* bq = (const float*)d_in[2];
    const float* Wk = (const float*)d_in[3];
    const float* bk = (const float*)d_in[4];
    const float* Wv = (const float*)d_in[5];
    const float* bv = (const float*)d_in[6];
    const float* Wo = (const float*)d_in[7];
    const float* bo = (const float*)d_in[8];
    float* out = (float*)d_out;

    __nv_bfloat16 *xh, *xl, *ah, *al;
    __nv_bfloat16 *wqh, *wql, *wkh, *wkl, *wvh, *wvl, *woh, *wol;
    float* attp;
    cudaGetSymbolAddress((void**)&xh,  g_xh);  cudaGetSymbolAddress((void**)&xl,  g_xl);
    cudaGetSymbolAddress((void**)&ah,  g_ah);  cudaGetSymbolAddress((void**)&al,  g_al);
    cudaGetSymbolAddress((void**)&wqh, g_wqh); cudaGetSymbolAddress((void**)&wql, g_wql);
    cudaGetSymbolAddress((void**)&wkh, g_wkh); cudaGetSymbolAddress((void**)&wkl, g_wkl);
    cudaGetSymbolAddress((void**)&wvh, g_wvh); cudaGetSymbolAddress((void**)&wvl, g_wvl);
    cudaGetSymbolAddress((void**)&woh, g_woh); cudaGetSymbolAddress((void**)&wol, g_wol);
    cudaGetSymbolAddress((void**)&attp, g_att);

    convert_hl<<<(MM*EE/4 + 255)/256, 256>>>(x,  xh,  xl,  MM*EE/4);
    convert_hl<<<(EE*EE/4 + 255)/256, 256>>>(Wq, wqh, wql, EE*EE/4);
    convert_hl<<<(EE*EE/4 + 255)/256, 256>>>(Wk, wkh, wkl, EE*EE/4);
    convert_hl<<<(EE*EE/4 + 255)/256, 256>>>(Wv, wvh, wvl, EE*EE/4);
    convert_hl<<<(EE*EE/4 + 255)/256, 256>>>(Wo, woh, wol, EE*EE/4);

    dim3 gp(MM/128, EE/128);
    gemm_mma<<<gp, 256>>>(xh, xl, wqh, wql, bq, nullptr, 0);
    gemm_mma<<<gp, 256>>>(xh, xl, wkh, wkl, bk, nullptr, 1);
    gemm_mma<<<gp, 256>>>(xh, xl, wvh, wvl, bv, nullptr, 2);

    size_t asmem = (size_t)4 * 64 * PAD * sizeof(float);
    cudaFuncSetAttribute(attn_kernel, cudaFuncAttributeMaxDynamicSharedMemorySize,
                         (int)asmem);
    attn_kernel<<<dim3(SS/64, BB*HH), 256, asmem>>>();

    convert_hl<<<(MM*EE/4 + 255)/256, 256>>>(attp, ah, al, MM*EE/4);
    gemm_mma<<<gp, 256>>>(ah, al, woh, wol, bo, out, -1);
}

// round 6
// speedup vs baseline: 3.7384x; 3.7384x over previous
#include <cuda_runtime.h>
#include <cuda_bf16.h>
#include <cstdint>

#define BB 2
#define SS 2048
#define EE 1024
#define HH 16
#define DD 64
#define MM (BB*SS)
#define GSTR 40            // gemm smem row stride (halves)
#define GS (128*GSTR)      // halves per gemm tile array
#define KSTR 72            // attn smem row stride (halves)
#define ATILE (64*KSTR)    // halves per attn tile array

typedef __nv_bfloat16 bf;

// ---------------- scratch (device globals: allocation-free rule) ------------
__device__ bf g_xh[MM*EE],  g_xl[MM*EE];
__device__ bf g_ah[MM*EE],  g_al[MM*EE];
__device__ bf g_wqh[EE*EE], g_wql[EE*EE];
__device__ bf g_wkh[EE*EE], g_wkl[EE*EE];
__device__ bf g_wvh[EE*EE], g_wvl[EE*EE];
__device__ bf g_woh[EE*EE], g_wol[EE*EE];
__device__ bf g_Qh[BB*HH*SS*DD], g_Ql[BB*HH*SS*DD];
__device__ bf g_Kh[BB*HH*SS*DD], g_Kl[BB*HH*SS*DD];
__device__ bf g_Vh[BB*HH*SS*DD], g_Vl[BB*HH*SS*DD];

// ---------------- helpers ---------------------------------------------------
__device__ __forceinline__ uint32_t smem_u32(const void* p) {
    uint32_t a;
    asm("{ .reg .u64 t; cvta.to.shared.u64 t, %1; cvt.u32.u64 %0, t; }" : "=r"(a) : "l"(p));
    return a;
}
__device__ __forceinline__ void ldsm_x4(uint32_t& r0, uint32_t& r1, uint32_t& r2,
                                        uint32_t& r3, uint32_t addr) {
    asm volatile("ldmatrix.sync.aligned.m8n8.x4.shared.b16 {%0,%1,%2,%3}, [%4];"
                 : "=r"(r0), "=r"(r1), "=r"(r2), "=r"(r3) : "r"(addr));
}
__device__ __forceinline__ void ldsm_x4t(uint32_t& r0, uint32_t& r1, uint32_t& r2,
                                         uint32_t& r3, uint32_t addr) {
    asm volatile("ldmatrix.sync.aligned.m8n8.x4.trans.shared.b16 {%0,%1,%2,%3}, [%4];"
                 : "=r"(r0), "=r"(r1), "=r"(r2), "=r"(r3) : "r"(addr));
}
__device__ __forceinline__ void mma_bf16(float* c, const uint32_t* a,
                                         uint32_t b0, uint32_t b1) {
    asm volatile(
        "mma.sync.aligned.m16n8k16.row.col.f32.bf16.bf16.f32 "
        "{%0,%1,%2,%3}, {%4,%5,%6,%7}, {%8,%9}, {%0,%1,%2,%3};"
        : "+f"(c[0]), "+f"(c[1]), "+f"(c[2]), "+f"(c[3])
        : "r"(a[0]), "r"(a[1]), "r"(a[2]), "r"(a[3]), "r"(b0), "r"(b1));
}
__device__ __forceinline__ void cpa16(uint32_t dst, const void* src) {
    asm volatile("cp.async.cg.shared.global [%0], [%1], 16;" :: "r"(dst), "l"(src));
}
#define CP_COMMIT() asm volatile("cp.async.commit_group;" ::: "memory")
#define CP_WAIT1()  asm volatile("cp.async.wait_group 1;" ::: "memory")
#define CP_WAIT0()  asm volatile("cp.async.wait_group 0;" ::: "memory")

// pack(lo=a, hi=b): low 16 bits <- bf16(a)
__device__ __forceinline__ uint32_t pack_bf(float a, float b) {
    uint32_t r;
    asm("cvt.rn.bf16x2.f32 %0, %1, %2;" : "=r"(r) : "f"(b), "f"(a));
    return r;
}
// split pair (a,b) into hi bf16x2 + lo bf16x2 residual
__device__ __forceinline__ void split2(float a, float b, uint32_t& hp, uint32_t& lp) {
    hp = pack_bf(a, b);
    float ha = __uint_as_float(hp << 16);
    float hb = __uint_as_float(hp & 0xFFFF0000u);
    lp = pack_bf(a - ha, b - hb);
}

// ---------------- fp32 -> (hi, lo) bf16 split conversion --------------------
__global__ __launch_bounds__(256) void convert_hl(
    const float* __restrict__ in, bf* __restrict__ hi, bf* __restrict__ lo, int n4)
{
    int i = blockIdx.x * blockDim.x + threadIdx.x;
    if (i >= n4) return;
    float4 v = ((const float4*)in)[i];
    uint32_t h0, l0, h1, l1;
    split2(v.x, v.y, h0, l0);
    split2(v.z, v.w, h1, l1);
    ((uint2*)hi)[i] = make_uint2(h0, h1);
    ((uint2*)lo)[i] = make_uint2(l0, l1);
}

// ---------------------------------------------------------------------------
// Pipelined split-bf16 GEMM: C[m,n] = sum_k A[m,k]*W[n,k] + bias[n]
// 128x128 CTA tile, BK=32, cp.async double buffer, 8 warps (64x32 tiles).
// sel 0/1/2: write split bf16 to Q/K/V [B,H,S,D] (Q scaled by 1/8);
// sel -1: f32 row-major Cout.
// ---------------------------------------------------------------------------
__global__ __launch_bounds__(256) void gemm_mma(
    const bf* __restrict__ Ah, const bf* __restrict__ Al,
    const bf* __restrict__ Bh, const bf* __restrict__ Bl,
    const float* __restrict__ bias, float* __restrict__ Cout, int sel)
{
    extern __shared__ bf smg[];
    const int t    = threadIdx.x;
    const int warp = t >> 5;
    const int lane = t & 31;
    const int row0 = blockIdx.x * 128;
    const int col0 = blockIdx.y * 128;
    const int wm   = (warp >> 2) * 64;
    const int wn   = (warp & 3) * 32;

    float acc[4][4][4];
#pragma unroll
    for (int mi = 0; mi < 4; mi++)
#pragma unroll
        for (int ni = 0; ni < 4; ni++)
#pragma unroll
            for (int k = 0; k < 4; k++) acc[mi][ni][k] = 0.f;

    const uint32_t sbase = smem_u32(smg);
    const int lr = t >> 1;
    const int lh = (t & 1) * 16;
    const bf* pA = Ah + (size_t)(row0 + lr) * EE + lh;
    const bf* pL = Al + (size_t)(row0 + lr) * EE + lh;
    const bf* pB = Bh + (size_t)(col0 + lr) * EE + lh;
    const bf* pM = Bl + (size_t)(col0 + lr) * EE + lh;
    const uint32_t drow = (uint32_t)(lr * GSTR + lh) * 2;

    auto load_stage = [&](int c, int s) {
        const uint32_t sb = sbase + (uint32_t)(s * 4 * GS) * 2 + drow;
        const int ko = c * 32;
        cpa16(sb,               pA + ko);  cpa16(sb + 16,               pA + ko + 8);
        cpa16(sb + GS*2,        pL + ko);  cpa16(sb + GS*2 + 16,        pL + ko + 8);
        cpa16(sb + 2*GS*2,      pB + ko);  cpa16(sb + 2*GS*2 + 16,      pB + ko + 8);
        cpa16(sb + 3*GS*2,      pM + ko);  cpa16(sb + 3*GS*2 + 16,      pM + ko + 8);
    };

    load_stage(0, 0);
    CP_COMMIT();

    const int a_row  = lane & 15;
    const int a_half = (lane >> 4) << 3;

    for (int c = 0; c < 32; c++) {
        if (c + 1 < 32) { load_stage(c + 1, (c + 1) & 1); CP_COMMIT(); }
        if (c + 1 < 32) { CP_WAIT1(); } else { CP_WAIT0(); }
        __syncthreads();

        const uint32_t uA  = sbase + (uint32_t)((c & 1) * 4 * GS) * 2;
        const uint32_t uAl = uA + GS * 2;
        const uint32_t uB  = uA + 2 * GS * 2;
        const uint32_t uBl = uA + 3 * GS * 2;

#pragma unroll
        for (int ks = 0; ks < 2; ks++) {
            const int kk = ks * 16;
            uint32_t bH[4][2], bL[4][2];
#pragma unroll
            for (int u = 0; u < 2; u++) {
                const uint32_t bo = (uint32_t)((wn + u*16 + a_row) * GSTR + kk + a_half) * 2;
                uint32_t r0, r1, r2, r3;
                ldsm_x4(r0, r1, r2, r3, uB + bo);
                bH[2*u][0] = r0; bH[2*u][1] = r2; bH[2*u+1][0] = r1; bH[2*u+1][1] = r3;
                ldsm_x4(r0, r1, r2, r3, uBl + bo);
                bL[2*u][0] = r0; bL[2*u][1] = r2; bL[2*u+1][0] = r1; bL[2*u+1][1] = r3;
            }
#pragma unroll
            for (int mi = 0; mi < 4; mi++) {
                const uint32_t ao = (uint32_t)((wm + mi*16 + a_row) * GSTR + kk + a_half) * 2;
                uint32_t aH[4], aL[4];
                ldsm_x4(aH[0], aH[1], aH[2], aH[3], uA  + ao);
                ldsm_x4(aL[0], aL[1], aL[2], aL[3], uAl + ao);
#pragma unroll
                for (int ni = 0; ni < 4; ni++) {
                    mma_bf16(acc[mi][ni], aH, bH[ni][0], bH[ni][1]);
                    mma_bf16(acc[mi][ni], aH, bL[ni][0], bL[ni][1]);
                    mma_bf16(acc[mi][ni], aL, bH[ni][0], bH[ni][1]);
                }
            }
        }
        __syncthreads();
    }

    // ---- epilogue ----
    const int gr = lane >> 2;
    const int gc = (lane & 3) * 2;
    const float qs = (sel == 0) ? 0.125f : 1.f;
    bf* oh = (sel == 0) ? g_Qh : (sel == 1) ? g_Kh : g_Vh;
    bf* ol = (sel == 0) ? g_Ql : (sel == 1) ? g_Kl : g_Vl;
#pragma unroll
    for (int mi = 0; mi < 4; mi++) {
#pragma unroll
        for (int ni = 0; ni < 4; ni++) {
#pragma unroll
            for (int half = 0; half < 2; half++) {
                const int m = row0 + wm + mi*16 + gr + half*8;
                const int n = col0 + wn + ni*8 + gc;
                float v0 = acc[mi][ni][half*2+0] + bias[n];
                float v1 = acc[mi][ni][half*2+1] + bias[n+1];
                if (sel < 0) {
                    *(float2*)&Cout[(size_t)m * EE + n] = make_float2(v0, v1);
                } else {
                    const int b = m >> 11, s = m & 2047;
                    const int h = n >> 6,  d = n & 63;
                    uint32_t hp, lp;
                    split2(v0 * qs, v1 * qs, hp, lp);
                    const size_t idx = ((((size_t)b*HH + h)*SS + s)*DD + d) >> 1;
                    ((uint32_t*)oh)[idx] = hp;
                    ((uint32_t*)ol)[idx] = lp;
                }
            }
        }
    }
}

// ---------------------------------------------------------------------------
// Tensor-core flash attention (split-bf16 mma.sync, fp32 online softmax).
// grid (S/128, B*H), 256 threads (8 warps x 16 query rows).
// Reads g_Q/K/V hi+lo [B,H,S,D]; writes O split bf16 to g_ah/g_al [M,E].
// ---------------------------------------------------------------------------
__global__ __launch_bounds__(256) void attn_mma()
{
    extern __shared__ bf sma[];
    const int t    = threadIdx.x;
    const int warp = t >> 5;
    const int lane = t & 31;
    const int bh   = blockIdx.y;
    const int q0   = blockIdx.x * 128;
    const int b    = bh >> 4;
    const int h    = bh & 15;

    const uint32_t sbase = smem_u32(sma);
    const size_t bhoff = (size_t)bh * SS * DD;

    // ---- preload Q a-frags (already scaled by 1/8 in projection) ----
    uint32_t aQh[4][4], aQl[4][4];
    {
        const bf* Qhp = g_Qh + bhoff;
        const bf* Qlp = g_Ql + bhoff;
#pragma unroll
        for (int ks = 0; ks < 4; ks++)
#pragma unroll
            for (int part = 0; part < 4; part++) {
                const int row = q0 + warp*16 + (lane >> 2) + (part & 1)*8;
                const int col = ks*16 + (part >> 1)*8 + (lane & 3)*2;
                aQh[ks][part] = *(const uint32_t*)(Qhp + (size_t)row*DD + col);
                aQl[ks][part] = *(const uint32_t*)(Qlp + (size_t)row*DD + col);
            }
    }

    // ---- K/V tile cp.async loaders: FULL-row coverage (fix for R5 NaN) ----
    // 64 rows x 64 halves. 4 threads/row, each thread loads 16 halves (2x16B).
    const int lrow = t >> 2;            // 0..63
    const int lchk = (t & 3) * 16;      // halves: 0,16,32,48
    const uint32_t ddst = (uint32_t)(lrow * KSTR + lchk) * 2;
    auto load_kv = [&](int kb, int s) {
        const size_t src = bhoff + (size_t)(kb*64 + lrow)*DD + lchk;
        const uint32_t sb = sbase + (uint32_t)(s * 4 * ATILE) * 2 + ddst;
        cpa16(sb,                 g_Kh + src);
        cpa16(sb + 16,            g_Kh + src + 8);
        cpa16(sb + ATILE*2,       g_Kl + src);
        cpa16(sb + ATILE*2 + 16,  g_Kl + src + 8);
        cpa16(sb + 2*ATILE*2,       g_Vh + src);
        cpa16(sb + 2*ATILE*2 + 16,  g_Vh + src + 8);
        cpa16(sb + 3*ATILE*2,       g_Vl + src);
        cpa16(sb + 3*ATILE*2 + 16,  g_Vl + src + 8);
    };

    float m0 = -1e30f, m1 = -1e30f, l0 = 0.f, l1 = 0.f;
    float oc[8][4];
#pragma unroll
    for (int ni = 0; ni < 8; ni++)
#pragma unroll
        for (int k = 0; k < 4; k++) oc[ni][k] = 0.f;

    load_kv(0, 0);
    CP_COMMIT();

    const int a_row  = lane & 15;
    const int a_half = (lane >> 4) << 3;
    const int g      = lane >> 3;            // trans-ldsm lane group
    const int t_row  = (g & 1)*8 + (lane & 7);
    const int t_col  = (g >> 1)*8;

    for (int kb = 0; kb < SS/64; kb++) {
        if (kb + 1 < SS/64) { load_kv(kb + 1, (kb + 1) & 1); CP_COMMIT(); }
        if (kb + 1 < SS/64) { CP_WAIT1(); } else { CP_WAIT0(); }
        __syncthreads();

        const uint32_t uKh = sbase + (uint32_t)((kb & 1) * 4 * ATILE) * 2;
        const uint32_t uKl = uKh + ATILE*2;
        const uint32_t uVh = uKh + 2*ATILE*2;
        const uint32_t uVl = uKh + 3*ATILE*2;

        // ---- S = Q K^T ----
        float sc[8][4];
#pragma unroll
        for (int ni = 0; ni < 8; ni++)
#pragma unroll
            for (int k = 0; k < 4; k++) sc[ni][k] = 0.f;

#pragma unroll
        for (int ks = 0; ks < 4; ks++) {
            const int kk = ks * 16;
#pragma unroll
            for (int u = 0; u < 4; u++) {
                const uint32_t bo = (uint32_t)((u*16 + a_row) * KSTR + kk + a_half) * 2;
                uint32_t r0, r1, r2, r3, s0, s1, s2, s3;
                ldsm_x4(r0, r1, r2, r3, uKh + bo);
                ldsm_x4(s0, s1, s2, s3, uKl + bo);
                mma_bf16(sc[2*u],   aQh[ks], r0, r2);
                mma_bf16(sc[2*u],   aQh[ks], s0, s2);
                mma_bf16(sc[2*u],   aQl[ks], r0, r2);
                mma_bf16(sc[2*u+1], aQh[ks], r1, r3);
                mma_bf16(sc[2*u+1], aQh[ks], s1, s3);
                mma_bf16(sc[2*u+1], aQl[ks], r1, r3);
            }
        }

        // ---- online softmax (rows r = lane>>2 and r+8) ----
        float mx0 = -1e30f, mx1 = -1e30f;
#pragma unroll
        for (int ni = 0; ni < 8; ni++) {
            mx0 = fmaxf(mx0, fmaxf(sc[ni][0], sc[ni][1]));
            mx1 = fmaxf(mx1, fmaxf(sc[ni][2], sc[ni][3]));
        }
        mx0 = fmaxf(mx0, __shfl_xor_sync(0xffffffffu, mx0, 1));
        mx0 = fmaxf(mx0, __shfl_xor_sync(0xffffffffu, mx0, 2));
        mx1 = fmaxf(mx1, __shfl_xor_sync(0xffffffffu, mx1, 1));
        mx1 = fmaxf(mx1, __shfl_xor_sync(0xffffffffu, mx1, 2));
        const float mn0 = fmaxf(m0, mx0), mn1 = fmaxf(m1, mx1);
        const float al0 = __expf(m0 - mn0), al1 = __expf(m1 - mn1);
        float s0 = 0.f, s1 = 0.f;
#pragma unroll
        for (int ni = 0; ni < 8; ni++) {
            sc[ni][0] = __expf(sc[ni][0] - mn0); s0 += sc[ni][0];
            sc[ni][1] = __expf(sc[ni][1] - mn0); s0 += sc[ni][1];
            sc[ni][2] = __expf(sc[ni][2] - mn1); s1 += sc[ni][2];
            sc[ni][3] = __expf(sc[ni][3] - mn1); s1 += sc[ni][3];
        }
        s0 += __shfl_xor_sync(0xffffffffu, s0, 1);
        s0 += __shfl_xor_sync(0xffffffffu, s0, 2);
        s1 += __shfl_xor_sync(0xffffffffu, s1, 1);
        s1 += __shfl_xor_sync(0xffffffffu, s1, 2);
        l0 = l0 * al0 + s0;  l1 = l1 * al1 + s1;
        m0 = mn0;            m1 = mn1;
#pragma unroll
        for (int ni = 0; ni < 8; ni++) {
            oc[ni][0] *= al0; oc[ni][1] *= al0;
            oc[ni][2] *= al1; oc[ni][3] *= al1;
        }

        // ---- O += P V ----
#pragma unroll
        for (int ks = 0; ks < 4; ks++) {
            uint32_t ph[4], pl[4];
            split2(sc[2*ks][0],   sc[2*ks][1],   ph[0], pl[0]);
            split2(sc[2*ks][2],   sc[2*ks][3],   ph[1], pl[1]);
            split2(sc[2*ks+1][0], sc[2*ks+1][1], ph[2], pl[2]);
            split2(sc[2*ks+1][2], sc[2*ks+1][3], ph[3], pl[3]);
            const int keyr = ks*16 + t_row;
#pragma unroll
            for (int p = 0; p < 4; p++) {
                const uint32_t vo = (uint32_t)(keyr * KSTR + 16*p + t_col) * 2;
                uint32_t v0, v1, v2, v3, w0, w1, w2, w3;
                ldsm_x4t(v0, v1, v2, v3, uVh + vo);
                ldsm_x4t(w0, w1, w2, w3, uVl + vo);
                mma_bf16(oc[2*p],   ph, v0, v1);
                mma_bf16(oc[2*p],   ph, w0, w1);
                mma_bf16(oc[2*p],   pl, v0, v1);
                mma_bf16(oc[2*p+1], ph, v2, v3);
                mma_bf16(oc[2*p+1], ph, w2, w3);
                mma_bf16(oc[2*p+1], pl, v2, v3);
            }
        }
        __syncthreads();
    }

    // ---- epilogue: normalize, split, write to g_ah/g_al [M,E] ----
    const float inv0 = 1.f / l0, inv1 = 1.f / l1;
    const int r0row = q0 + warp*16 + (lane >> 2);
#pragma unroll
    for (int ni = 0; ni < 8; ni++) {
        const int d = ni*8 + (lane & 3)*2;
        const size_t col = (size_t)h*DD + d;
        uint32_t hp, lp;
        split2(oc[ni][0]*inv0, oc[ni][1]*inv0, hp, lp);
        size_t idx = (((size_t)b*SS + r0row)*EE + col) >> 1;
        ((uint32_t*)g_ah)[idx] = hp;
        ((uint32_t*)g_al)[idx] = lp;
        split2(oc[ni][2]*inv1, oc[ni][3]*inv1, hp, lp);
        idx = (((size_t)b*SS + r0row + 8)*EE + col) >> 1;
        ((uint32_t*)g_ah)[idx] = hp;
        ((uint32_t*)g_al)[idx] = lp;
    }
}

// ---------------------------------------------------------------------------
extern "C" void kernel_launch(void* const* d_in, const int* in_sizes, int n_in,
                              void* d_out, int out_size)
{
    const float* x  = (const float*)d_in[0];
    const float* Wq = (const float*)d_in[1];
    const float* bq = (const float*)d_in[2];
    const float* Wk = (const float*)d_in[3];
    const float* bk = (const float*)d_in[4];
    const float* Wv = (const float*)d_in[5];
    const float* bv = (const float*)d_in[6];
    const float* Wo = (const float*)d_in[7];
    const float* bo = (const float*)d_in[8];
    float* out = (float*)d_out;

    bf *xh, *xl, *ah, *al;
    bf *wqh, *wql, *wkh, *wkl, *wvh, *wvl, *woh, *wol;
    cudaGetSymbolAddress((void**)&xh,  g_xh);  cudaGetSymbolAddress((void**)&xl,  g_xl);
    cudaGetSymbolAddress((void**)&ah,  g_ah);  cudaGetSymbolAddress((void**)&al,  g_al);
    cudaGetSymbolAddress((void**)&wqh, g_wqh); cudaGetSymbolAddress((void**)&wql, g_wql);
    cudaGetSymbolAddress((void**)&wkh, g_wkh); cudaGetSymbolAddress((void**)&wkl, g_wkl);
    cudaGetSymbolAddress((void**)&wvh, g_wvh); cudaGetSymbolAddress((void**)&wvl, g_wvl);
    cudaGetSymbolAddress((void**)&woh, g_woh); cudaGetSymbolAddress((void**)&wol, g_wol);

    convert_hl<<<(MM*EE/4 + 255)/256, 256>>>(x,  xh,  xl,  MM*EE/4);
    convert_hl<<<(EE*EE/4 + 255)/256, 256>>>(Wq, wqh, wql, EE*EE/4);
    convert_hl<<<(EE*EE/4 + 255)/256, 256>>>(Wk, wkh, wkl, EE*EE/4);
    convert_hl<<<(EE*EE/4 + 255)/256, 256>>>(Wv, wvh, wvl, EE*EE/4);
    convert_hl<<<(EE*EE/4 + 255)/256, 256>>>(Wo, woh, wol, EE*EE/4);

    const int gsmem = 2 * 4 * GS * 2;       // 81,920 B
    const int asmem = 2 * 4 * ATILE * 2;    // 73,728 B
    cudaFuncSetAttribute(gemm_mma, cudaFuncAttributeMaxDynamicSharedMemorySize, gsmem);
    cudaFuncSetAttribute(attn_mma, cudaFuncAttributeMaxDynamicSharedMemorySize, asmem);

    dim3 gp(MM/128, EE/128);
    gemm_mma<<<gp, 256, gsmem>>>(xh, xl, wqh, wql, bq, nullptr, 0);
    gemm_mma<<<gp, 256, gsmem>>>(xh, xl, wkh, wkl, bk, nullptr, 1);
    gemm_mma<<<gp, 256, gsmem>>>(xh, xl, wvh, wvl, bv, nullptr, 2);

    attn_mma<<<dim3(SS/128, BB*HH), 256, asmem>>>();

    gemm_mma<<<gp, 256, gsmem>>>(ah, al, woh, wol, bo, out, -1);
}

// round 9
// speedup vs baseline: 4.1667x; 1.1146x over previous
#include <cuda_runtime.h>
#include <cuda_bf16.h>
#include <cstdint>

#define BB 2
#define SS 2048
#define EE 1024
#define HH 16
#define DD 64
#define MM (BB*SS)
#define GSTR 40            // gemm smem row stride (halves)
#define GS (128*GSTR)      // halves per gemm tile array
#define KSTR 72            // attn smem row stride (halves)
#define ATILE (64*KSTR)    // halves per attn K/V tile array
#define QTILE (128*KSTR)   // halves per attn Q tile array
#define LOG2E 1.4426950408889634f

typedef __nv_bfloat16 bf;

// ---------------- scratch (device globals: allocation-free rule) ------------
__device__ bf g_xh[MM*EE],  g_xl[MM*EE];
__device__ bf g_ah[MM*EE],  g_al[MM*EE];
__device__ bf g_wqh[EE*EE], g_wql[EE*EE];
__device__ bf g_wkh[EE*EE], g_wkl[EE*EE];
__device__ bf g_wvh[EE*EE], g_wvl[EE*EE];
__device__ bf g_woh[EE*EE], g_wol[EE*EE];
__device__ bf g_Qh[BB*HH*SS*DD], g_Ql[BB*HH*SS*DD];
__device__ bf g_Kh[BB*HH*SS*DD], g_Kl[BB*HH*SS*DD];
__device__ bf g_Vh[BB*HH*SS*DD], g_Vl[BB*HH*SS*DD];

// ---------------- helpers ---------------------------------------------------
__device__ __forceinline__ uint32_t smem_u32(const void* p) {
    uint32_t a;
    asm("{ .reg .u64 t; cvta.to.shared.u64 t, %1; cvt.u32.u64 %0, t; }" : "=r"(a) : "l"(p));
    return a;
}
__device__ __forceinline__ void ldsm_x4(uint32_t& r0, uint32_t& r1, uint32_t& r2,
                                        uint32_t& r3, uint32_t addr) {
    asm volatile("ldmatrix.sync.aligned.m8n8.x4.shared.b16 {%0,%1,%2,%3}, [%4];"
                 : "=r"(r0), "=r"(r1), "=r"(r2), "=r"(r3) : "r"(addr));
}
__device__ __forceinline__ void ldsm_x4t(uint32_t& r0, uint32_t& r1, uint32_t& r2,
                                         uint32_t& r3, uint32_t addr) {
    asm volatile("ldmatrix.sync.aligned.m8n8.x4.trans.shared.b16 {%0,%1,%2,%3}, [%4];"
                 : "=r"(r0), "=r"(r1), "=r"(r2), "=r"(r3) : "r"(addr));
}
__device__ __forceinline__ void mma_bf16(float* c, const uint32_t* a,
                                         uint32_t b0, uint32_t b1) {
    asm volatile(
        "mma.sync.aligned.m16n8k16.row.col.f32.bf16.bf16.f32 "
        "{%0,%1,%2,%3}, {%4,%5,%6,%7}, {%8,%9}, {%0,%1,%2,%3};"
        : "+f"(c[0]), "+f"(c[1]), "+f"(c[2]), "+f"(c[3])
        : "r"(a[0]), "r"(a[1]), "r"(a[2]), "r"(a[3]), "r"(b0), "r"(b1));
}
__device__ __forceinline__ void cpa16(uint32_t dst, const void* src) {
    asm volatile("cp.async.cg.shared.global [%0], [%1], 16;" :: "r"(dst), "l"(src));
}
#define CP_COMMIT() asm volatile("cp.async.commit_group;" ::: "memory")
#define CP_WAIT1()  asm volatile("cp.async.wait_group 1;" ::: "memory")
#define CP_WAIT0()  asm volatile("cp.async.wait_group 0;" ::: "memory")

__device__ __forceinline__ float ex2(float x) {
    float r;
    asm("ex2.approx.f32 %0, %1;" : "=f"(r) : "f"(x));
    return r;
}
// pack(lo=a, hi=b): low 16 bits <- bf16(a)
__device__ __forceinline__ uint32_t pack_bf(float a, float b) {
    uint32_t r;
    asm("cvt.rn.bf16x2.f32 %0, %1, %2;" : "=r"(r) : "f"(b), "f"(a));
    return r;
}
// split pair (a,b) into hi bf16x2 + lo bf16x2 residual
__device__ __forceinline__ void split2(float a, float b, uint32_t& hp, uint32_t& lp) {
    hp = pack_bf(a, b);
    float ha = __uint_as_float(hp << 16);
    float hb = __uint_as_float(hp & 0xFFFF0000u);
    lp = pack_bf(a - ha, b - hb);
}

// ---------------- fp32 -> (hi, lo) bf16 split conversion --------------------
__global__ __launch_bounds__(256) void convert_hl(
    const float* __restrict__ in, bf* __restrict__ hi, bf* __restrict__ lo, int n4)
{
    int i = blockIdx.x * blockDim.x + threadIdx.x;
    if (i >= n4) return;
    float4 v = ((const float4*)in)[i];
    uint32_t h0, l0, h1, l1;
    split2(v.x, v.y, h0, l0);
    split2(v.z, v.w, h1, l1);
    ((uint2*)hi)[i] = make_uint2(h0, h1);
    ((uint2*)lo)[i] = make_uint2(l0, l1);
}

// ---------------------------------------------------------------------------
// Pipelined split-bf16 GEMM: C[m,n] = sum_k A[m,k]*W[n,k] + bias[n]
// 128x128 CTA tile, BK=32, cp.async double buffer, 8 warps (64x32 tiles).
// sel 0/1/2: write split bf16 to Q/K/V [B,H,S,D] (Q scaled by log2e/8);
// sel -1: f32 row-major Cout.
// ---------------------------------------------------------------------------
__global__ __launch_bounds__(256, 2) void gemm_mma(
    const bf* __restrict__ Ah, const bf* __restrict__ Al,
    const bf* __restrict__ Bh, const bf* __restrict__ Bl,
    const float* __restrict__ bias, float* __restrict__ Cout, int sel)
{
    extern __shared__ bf smg[];
    const int t    = threadIdx.x;
    const int warp = t >> 5;
    const int lane = t & 31;
    const int row0 = blockIdx.x * 128;
    const int col0 = blockIdx.y * 128;
    const int wm   = (warp >> 2) * 64;
    const int wn   = (warp & 3) * 32;

    float acc[4][4][4];
#pragma unroll
    for (int mi = 0; mi < 4; mi++)
#pragma unroll
        for (int ni = 0; ni < 4; ni++)
#pragma unroll
            for (int k = 0; k < 4; k++) acc[mi][ni][k] = 0.f;

    const uint32_t sbase = smem_u32(smg);
    const int lr = t >> 1;
    const int lh = (t & 1) * 16;
    const bf* pA = Ah + (size_t)(row0 + lr) * EE + lh;
    const bf* pL = Al + (size_t)(row0 + lr) * EE + lh;
    const bf* pB = Bh + (size_t)(col0 + lr) * EE + lh;
    const bf* pM = Bl + (size_t)(col0 + lr) * EE + lh;
    const uint32_t drow = (uint32_t)(lr * GSTR + lh) * 2;

    auto load_stage = [&](int c, int s) {
        const uint32_t sb = sbase + (uint32_t)(s * 4 * GS) * 2 + drow;
        const int ko = c * 32;
        cpa16(sb,               pA + ko);  cpa16(sb + 16,               pA + ko + 8);
        cpa16(sb + GS*2,        pL + ko);  cpa16(sb + GS*2 + 16,        pL + ko + 8);
        cpa16(sb + 2*GS*2,      pB + ko);  cpa16(sb + 2*GS*2 + 16,      pB + ko + 8);
        cpa16(sb + 3*GS*2,      pM + ko);  cpa16(sb + 3*GS*2 + 16,      pM + ko + 8);
    };

    load_stage(0, 0);
    CP_COMMIT();

    const int a_row  = lane & 15;
    const int a_half = (lane >> 4) << 3;

    for (int c = 0; c < 32; c++) {
        if (c + 1 < 32) { load_stage(c + 1, (c + 1) & 1); CP_COMMIT(); }
        if (c + 1 < 32) { CP_WAIT1(); } else { CP_WAIT0(); }
        __syncthreads();

        const uint32_t uA  = sbase + (uint32_t)((c & 1) * 4 * GS) * 2;
        const uint32_t uAl = uA + GS * 2;
        const uint32_t uB  = uA + 2 * GS * 2;
        const uint32_t uBl = uA + 3 * GS * 2;

#pragma unroll
        for (int ks = 0; ks < 2; ks++) {
            const int kk = ks * 16;
            uint32_t bH[4][2], bL[4][2];
#pragma unroll
            for (int u = 0; u < 2; u++) {
                const uint32_t bo = (uint32_t)((wn + u*16 + a_row) * GSTR + kk + a_half) * 2;
                uint32_t r0, r1, r2, r3;
                ldsm_x4(r0, r1, r2, r3, uB + bo);
                bH[2*u][0] = r0; bH[2*u][1] = r2; bH[2*u+1][0] = r1; bH[2*u+1][1] = r3;
                ldsm_x4(r0, r1, r2, r3, uBl + bo);
                bL[2*u][0] = r0; bL[2*u][1] = r2; bL[2*u+1][0] = r1; bL[2*u+1][1] = r3;
            }
#pragma unroll
            for (int mi = 0; mi < 4; mi++) {
                const uint32_t ao = (uint32_t)((wm + mi*16 + a_row) * GSTR + kk + a_half) * 2;
                uint32_t aH[4], aL[4];
                ldsm_x4(aH[0], aH[1], aH[2], aH[3], uA  + ao);
                ldsm_x4(aL[0], aL[1], aL[2], aL[3], uAl + ao);
#pragma unroll
                for (int ni = 0; ni < 4; ni++) {
                    mma_bf16(acc[mi][ni], aH, bH[ni][0], bH[ni][1]);
                    mma_bf16(acc[mi][ni], aH, bL[ni][0], bL[ni][1]);
                    mma_bf16(acc[mi][ni], aL, bH[ni][0], bH[ni][1]);
                }
            }
        }
        __syncthreads();
    }

    // ---- epilogue ----
    const int gr = lane >> 2;
    const int gc = (lane & 3) * 2;
    const float qs = (sel == 0) ? (0.125f * LOG2E) : 1.f;   // fold log2e into Q
    bf* oh = (sel == 0) ? g_Qh : (sel == 1) ? g_Kh : g_Vh;
    bf* ol = (sel == 0) ? g_Ql : (sel == 1) ? g_Kl : g_Vl;
#pragma unroll
    for (int mi = 0; mi < 4; mi++) {
#pragma unroll
        for (int ni = 0; ni < 4; ni++) {
#pragma unroll
            for (int half = 0; half < 2; half++) {
                const int m = row0 + wm + mi*16 + gr + half*8;
                const int n = col0 + wn + ni*8 + gc;
                float v0 = acc[mi][ni][half*2+0] + bias[n];
                float v1 = acc[mi][ni][half*2+1] + bias[n+1];
                if (sel < 0) {
                    *(float2*)&Cout[(size_t)m * EE + n] = make_float2(v0, v1);
                } else {
                    const int b = m >> 11, s = m & 2047;
                    const int h = n >> 6,  d = n & 63;
                    uint32_t hp, lp;
                    split2(v0 * qs, v1 * qs, hp, lp);
                    const size_t idx = ((((size_t)b*HH + h)*SS + s)*DD + d) >> 1;
                    ((uint32_t*)oh)[idx] = hp;
                    ((uint32_t*)ol)[idx] = lp;
                }
            }
        }
    }
}

// ---------------------------------------------------------------------------
// Tensor-core flash attention (split-bf16 mma.sync, base-2 online softmax).
// grid (S/128, B*H), 256 threads (8 warps x 16 query rows), 2 CTAs/SM.
// Q hi/lo staged in smem (frees regs for occupancy). K/V double-buffered.
// ---------------------------------------------------------------------------
__global__ __launch_bounds__(256, 2) void attn_mma()
{
    extern __shared__ bf sma[];
    const int t    = threadIdx.x;
    const int warp = t >> 5;
    const int lane = t & 31;
    const int bh   = blockIdx.y;
    const int q0   = blockIdx.x * 128;
    const int b    = bh >> 4;
    const int h    = bh & 15;

    const uint32_t sbase = smem_u32(sma);
    const uint32_t uQh = sbase;
    const uint32_t uQl = sbase + QTILE*2;
    const size_t bhoff = (size_t)bh * SS * DD;

    // ---- Q tile -> smem via cp.async (2 threads/row, 32 halves each) ----
    {
        const int qrow = t >> 1;
        const int qch  = (t & 1) * 32;
        const size_t src = bhoff + (size_t)(q0 + qrow)*DD + qch;
        const uint32_t dst = sbase + (uint32_t)(qrow * KSTR + qch) * 2;
#pragma unroll
        for (int c = 0; c < 32; c += 8) {
            cpa16(dst + c*2,            g_Qh + src + c);
            cpa16(dst + QTILE*2 + c*2,  g_Ql + src + c);
        }
    }

    // ---- K/V tile cp.async loaders (full-row coverage) ----
    const int lrow = t >> 2;            // 0..63
    const int lchk = (t & 3) * 16;      // halves: 0,16,32,48
    const uint32_t ddst = (uint32_t)(lrow * KSTR + lchk) * 2;
    auto load_kv = [&](int kb, int s) {
        const size_t src = bhoff + (size_t)(kb*64 + lrow)*DD + lchk;
        const uint32_t sb = sbase + (uint32_t)(2*QTILE + s * 4 * ATILE) * 2 + ddst;
        cpa16(sb,                 g_Kh + src);
        cpa16(sb + 16,            g_Kh + src + 8);
        cpa16(sb + ATILE*2,       g_Kl + src);
        cpa16(sb + ATILE*2 + 16,  g_Kl + src + 8);
        cpa16(sb + 2*ATILE*2,       g_Vh + src);
        cpa16(sb + 2*ATILE*2 + 16,  g_Vh + src + 8);
        cpa16(sb + 3*ATILE*2,       g_Vl + src);
        cpa16(sb + 3*ATILE*2 + 16,  g_Vl + src + 8);
    };

    float m0 = -1e30f, m1 = -1e30f, l0 = 0.f, l1 = 0.f;
    float oc[8][4];
#pragma unroll
    for (int ni = 0; ni < 8; ni++)
#pragma unroll
        for (int k = 0; k < 4; k++) oc[ni][k] = 0.f;

    load_kv(0, 0);
    CP_COMMIT();

    const int a_row  = lane & 15;
    const int a_half = (lane >> 4) << 3;
    const int g      = lane >> 3;            // trans-ldsm lane group
    const int t_row  = (g & 1)*8 + (lane & 7);
    const int t_col  = (g >> 1)*8;

    for (int kb = 0; kb < SS/64; kb++) {
        if (kb + 1 < SS/64) { load_kv(kb + 1, (kb + 1) & 1); CP_COMMIT(); }
        if (kb + 1 < SS/64) { CP_WAIT1(); } else { CP_WAIT0(); }
        __syncthreads();

        const uint32_t uKh = sbase + (uint32_t)(2*QTILE + (kb & 1) * 4 * ATILE) * 2;
        const uint32_t uKl = uKh + ATILE*2;
        const uint32_t uVh = uKh + 2*ATILE*2;
        const uint32_t uVl = uKh + 3*ATILE*2;

        // ---- S = Q K^T (log2 domain) ----
        float sc[8][4];
#pragma unroll
        for (int ni = 0; ni < 8; ni++)
#pragma unroll
            for (int k = 0; k < 4; k++) sc[ni][k] = 0.f;

#pragma unroll
        for (int ks = 0; ks < 4; ks++) {
            const int kk = ks * 16;
            const uint32_t qo = (uint32_t)((warp*16 + a_row) * KSTR + kk + a_half) * 2;
            uint32_t qh[4], ql[4];
            ldsm_x4(qh[0], qh[1], qh[2], qh[3], uQh + qo);
            ldsm_x4(ql[0], ql[1], ql[2], ql[3], uQl + qo);
#pragma unroll
            for (int u = 0; u < 4; u++) {
                const uint32_t bo = (uint32_t)((u*16 + a_row) * KSTR + kk + a_half) * 2;
                uint32_t r0, r1, r2, r3, s0, s1, s2, s3;
                ldsm_x4(r0, r1, r2, r3, uKh + bo);
                ldsm_x4(s0, s1, s2, s3, uKl + bo);
                mma_bf16(sc[2*u],   qh, r0, r2);
                mma_bf16(sc[2*u],   qh, s0, s2);
                mma_bf16(sc[2*u],   ql, r0, r2);
                mma_bf16(sc[2*u+1], qh, r1, r3);
                mma_bf16(sc[2*u+1], qh, s1, s3);
                mma_bf16(sc[2*u+1], ql, r1, r3);
            }
        }

        // ---- base-2 online softmax (rows r = lane>>2 and r+8) ----
        float mx0 = -1e30f, mx1 = -1e30f;
#pragma unroll
        for (int ni = 0; ni < 8; ni++) {
            mx0 = fmaxf(mx0, fmaxf(sc[ni][0], sc[ni][1]));
            mx1 = fmaxf(mx1, fmaxf(sc[ni][2], sc[ni][3]));
        }
        mx0 = fmaxf(mx0, __shfl_xor_sync(0xffffffffu, mx0, 1));
        mx0 = fmaxf(mx0, __shfl_xor_sync(0xffffffffu, mx0, 2));
        mx1 = fmaxf(mx1, __shfl_xor_sync(0xffffffffu, mx1, 1));
        mx1 = fmaxf(mx1, __shfl_xor_sync(0xffffffffu, mx1, 2));
        const float mn0 = fmaxf(m0, mx0), mn1 = fmaxf(m1, mx1);
        const float al0 = ex2(m0 - mn0), al1 = ex2(m1 - mn1);
        float s0 = 0.f, s1 = 0.f;
#pragma unroll
        for (int ni = 0; ni < 8; ni++) {
            sc[ni][0] = ex2(sc[ni][0] - mn0); s0 += sc[ni][0];
            sc[ni][1] = ex2(sc[ni][1] - mn0); s0 += sc[ni][1];
            sc[ni][2] = ex2(sc[ni][2] - mn1); s1 += sc[ni][2];
            sc[ni][3] = ex2(sc[ni][3] - mn1); s1 += sc[ni][3];
        }
        s0 += __shfl_xor_sync(0xffffffffu, s0, 1);
        s0 += __shfl_xor_sync(0xffffffffu, s0, 2);
        s1 += __shfl_xor_sync(0xffffffffu, s1, 1);
        s1 += __shfl_xor_sync(0xffffffffu, s1, 2);
        l0 = l0 * al0 + s0;  l1 = l1 * al1 + s1;
        m0 = mn0;            m1 = mn1;
#pragma unroll
        for (int ni = 0; ni < 8; ni++) {
            oc[ni][0] *= al0; oc[ni][1] *= al0;
            oc[ni][2] *= al1; oc[ni][3] *= al1;
        }

        // ---- O += P V ----
#pragma unroll
        for (int ks = 0; ks < 4; ks++) {
            uint32_t ph[4], pl[4];
            split2(sc[2*ks][0],   sc[2*ks][1],   ph[0], pl[0]);
            split2(sc[2*ks][2],   sc[2*ks][3],   ph[1], pl[1]);
            split2(sc[2*ks+1][0], sc[2*ks+1][1], ph[2], pl[2]);
            split2(sc[2*ks+1][2], sc[2*ks+1][3], ph[3], pl[3]);
            const int keyr = ks*16 + t_row;
#pragma unroll
            for (int p = 0; p < 4; p++) {
                const uint32_t vo = (uint32_t)(keyr * KSTR + 16*p + t_col) * 2;
                uint32_t v0, v1, v2, v3, w0, w1, w2, w3;
                ldsm_x4t(v0, v1, v2, v3, uVh + vo);
                ldsm_x4t(w0, w1, w2, w3, uVl + vo);
                mma_bf16(oc[2*p],   ph, v0, v1);
                mma_bf16(oc[2*p],   ph, w0, w1);
                mma_bf16(oc[2*p],   pl, v0, v1);
                mma_bf16(oc[2*p+1], ph, v2, v3);
                mma_bf16(oc[2*p+1], ph, w2, w3);
                mma_bf16(oc[2*p+1], pl, v2, v3);
            }
        }
        __syncthreads();
    }

    // ---- epilogue: normalize, split, write to g_ah/g_al [M,E] ----
    const float inv0 = 1.f / l0, inv1 = 1.f / l1;
    const int r0row = q0 + warp*16 + (lane >> 2);
#pragma unroll
    for (int ni = 0; ni < 8; ni++) {
        const int d = ni*8 + (lane & 3)*2;
        const size_t col = (size_t)h*DD + d;
        uint32_t hp, lp;
        split2(oc[ni][0]*inv0, oc[ni][1]*inv0, hp, lp);
        size_t idx = (((size_t)b*SS + r0row)*EE + col) >> 1;
        ((uint32_t*)g_ah)[idx] = hp;
        ((uint32_t*)g_al)[idx] = lp;
        split2(oc[ni][2]*inv1, oc[ni][3]*inv1, hp, lp);
        idx = (((size_t)b*SS + r0row + 8)*EE + col) >> 1;
        ((uint32_t*)g_ah)[idx] = hp;
        ((uint32_t*)g_al)[idx] = lp;
    }
}

// ---------------------------------------------------------------------------
extern "C" void kernel_launch(void* const* d_in, const int* in_sizes, int n_in,
                              void* d_out, int out_size)
{
    const float* x  = (const float*)d_in[0];
    const float* Wq = (const float*)d_in[1];
    const float* bq = (const float*)d_in[2];
    const float* Wk = (const float*)d_in[3];
    const float* bk = (const float*)d_in[4];
    const float* Wv = (const float*)d_in[5];
    const float* bv = (const float*)d_in[6];
    const float* Wo = (const float*)d_in[7];
    const float* bo = (const float*)d_in[8];
    float* out = (float*)d_out;

    bf *xh, *xl, *ah, *al;
    bf *wqh, *wql, *wkh, *wkl, *wvh, *wvl, *woh, *wol;
    cudaGetSymbolAddress((void**)&xh,  g_xh);  cudaGetSymbolAddress((void**)&xl,  g_xl);
    cudaGetSymbolAddress((void**)&ah,  g_ah);  cudaGetSymbolAddress((void**)&al,  g_al);
    cudaGetSymbolAddress((void**)&wqh, g_wqh); cudaGetSymbolAddress((void**)&wql, g_wql);
    cudaGetSymbolAddress((void**)&wkh, g_wkh); cudaGetSymbolAddress((void**)&wkl, g_wkl);
    cudaGetSymbolAddress((void**)&wvh, g_wvh); cudaGetSymbolAddress((void**)&wvl, g_wvl);
    cudaGetSymbolAddress((void**)&woh, g_woh); cudaGetSymbolAddress((void**)&wol, g_wol);

    convert_hl<<<(MM*EE/4 + 255)/256, 256>>>(x,  xh,  xl,  MM*EE/4);
    convert_hl<<<(EE*EE/4 + 255)/256, 256>>>(Wq, wqh, wql, EE*EE/4);
    convert_hl<<<(EE*EE/4 + 255)/256, 256>>>(Wk, wkh, wkl, EE*EE/4);
    convert_hl<<<(EE*EE/4 + 255)/256, 256>>>(Wv, wvh, wvl, EE*EE/4);
    convert_hl<<<(EE*EE/4 + 255)/256, 256>>>(Wo, woh, wol, EE*EE/4);

    const int gsmem = 2 * 4 * GS * 2;                    // 81,920 B
    const int asmem = (2*QTILE + 2 * 4 * ATILE) * 2;     // 110,592 B
    cudaFuncSetAttribute(gemm_mma, cudaFuncAttributeMaxDynamicSharedMemorySize, gsmem);
    cudaFuncSetAttribute(attn_mma, cudaFuncAttributeMaxDynamicSharedMemorySize, asmem);

    dim3 gp(MM/128, EE/128);
    gemm_mma<<<gp, 256, gsmem>>>(xh, xl, wqh, wql, bq, nullptr, 0);
    gemm_mma<<<gp, 256, gsmem>>>(xh, xl, wkh, wkl, bk, nullptr, 1);
    gemm_mma<<<gp, 256, gsmem>>>(xh, xl, wvh, wvl, bv, nullptr, 2);

    attn_mma<<<dim3(SS/128, BB*HH), 256, asmem>>>();

    gemm_mma<<<gp, 256, gsmem>>>(ah, al, woh, wol, bo, out, -1);
}

// round 10
// speedup vs baseline: 5.7658x; 1.3838x over previous
#include <cuda_runtime.h>
#include <cuda_fp16.h>
#include <cstdint>

#define BB 2
#define SS 2048
#define EE 1024
#define HH 16
#define DD 64
#define MM (BB*SS)
#define GSTR 40            // gemm smem row stride (halves)
#define GS (128*GSTR)      // halves per gemm tile array
#define KSTR 72            // attn smem row stride (halves)
#define ATILE (64*KSTR)    // halves per attn K/V tile array
#define QTILE (128*KSTR)   // halves per attn Q tile array
#define LOG2E 1.4426950408889634f

// ---------------- scratch (device globals: allocation-free rule) ------------
__device__ half g_x[MM*EE];                 // x, fp16 (A-side: hi only)
__device__ half g_att[MM*EE];               // attention out, fp16 (A-side)
__device__ half g_wqh[EE*EE], g_wql[EE*EE];
__device__ half g_wkh[EE*EE], g_wkl[EE*EE];
__device__ half g_wvh[EE*EE], g_wvl[EE*EE];
__device__ half g_woh[EE*EE], g_wol[EE*EE];
__device__ half g_Q[BB*HH*SS*DD];           // A-side (pre-scaled by log2e/8)
__device__ half g_Kh[BB*HH*SS*DD], g_Kl[BB*HH*SS*DD];
__device__ half g_Vh[BB*HH*SS*DD], g_Vl[BB*HH*SS*DD];

// ---------------- helpers ---------------------------------------------------
__device__ __forceinline__ uint32_t smem_u32(const void* p) {
    uint32_t a;
    asm("{ .reg .u64 t; cvta.to.shared.u64 t, %1; cvt.u32.u64 %0, t; }" : "=r"(a) : "l"(p));
    return a;
}
__device__ __forceinline__ void ldsm_x4(uint32_t& r0, uint32_t& r1, uint32_t& r2,
                                        uint32_t& r3, uint32_t addr) {
    asm volatile("ldmatrix.sync.aligned.m8n8.x4.shared.b16 {%0,%1,%2,%3}, [%4];"
                 : "=r"(r0), "=r"(r1), "=r"(r2), "=r"(r3) : "r"(addr));
}
__device__ __forceinline__ void ldsm_x4t(uint32_t& r0, uint32_t& r1, uint32_t& r2,
                                         uint32_t& r3, uint32_t addr) {
    asm volatile("ldmatrix.sync.aligned.m8n8.x4.trans.shared.b16 {%0,%1,%2,%3}, [%4];"
                 : "=r"(r0), "=r"(r1), "=r"(r2), "=r"(r3) : "r"(addr));
}
__device__ __forceinline__ void mma_f16(float* c, const uint32_t* a,
                                        uint32_t b0, uint32_t b1) {
    asm volatile(
        "mma.sync.aligned.m16n8k16.row.col.f32.f16.f16.f32 "
        "{%0,%1,%2,%3}, {%4,%5,%6,%7}, {%8,%9}, {%0,%1,%2,%3};"
        : "+f"(c[0]), "+f"(c[1]), "+f"(c[2]), "+f"(c[3])
        : "r"(a[0]), "r"(a[1]), "r"(a[2]), "r"(a[3]), "r"(b0), "r"(b1));
}
__device__ __forceinline__ void cpa16(uint32_t dst, const void* src) {
    asm volatile("cp.async.cg.shared.global [%0], [%1], 16;" :: "r"(dst), "l"(src));
}
#define CP_COMMIT() asm volatile("cp.async.commit_group;" ::: "memory")
#define CP_WAIT1()  asm volatile("cp.async.wait_group 1;" ::: "memory")
#define CP_WAIT0()  asm volatile("cp.async.wait_group 0;" ::: "memory")

__device__ __forceinline__ float ex2(float x) {
    float r;
    asm("ex2.approx.f32 %0, %1;" : "=f"(r) : "f"(x));
    return r;
}
__device__ __forceinline__ uint32_t pack_h2(float a, float b) {
    __half2 h = __floats2half2_rn(a, b);
    return *(uint32_t*)&h;
}
__device__ __forceinline__ void split2h(float a, float b, uint32_t& hp, uint32_t& lp) {
    __half2 h = __floats2half2_rn(a, b);
    float2 f = __half22float2(h);
    hp = *(uint32_t*)&h;
    __half2 l = __floats2half2_rn(a - f.x, b - f.y);
    lp = *(uint32_t*)&l;
}

// ---------------- conversion kernels ----------------------------------------
__global__ __launch_bounds__(256) void conv_h(
    const float* __restrict__ in, half* __restrict__ out, int n4)
{
    int i = blockIdx.x * blockDim.x + threadIdx.x;
    if (i >= n4) return;
    float4 v = ((const float4*)in)[i];
    ((uint2*)out)[i] = make_uint2(pack_h2(v.x, v.y), pack_h2(v.z, v.w));
}
__global__ __launch_bounds__(256) void conv_hl(
    const float* __restrict__ in, half* __restrict__ hi, half* __restrict__ lo, int n4)
{
    int i = blockIdx.x * blockDim.x + threadIdx.x;
    if (i >= n4) return;
    float4 v = ((const float4*)in)[i];
    uint32_t h0, l0, h1, l1;
    split2h(v.x, v.y, h0, l0);
    split2h(v.z, v.w, h1, l1);
    ((uint2*)hi)[i] = make_uint2(h0, h1);
    ((uint2*)lo)[i] = make_uint2(l0, l1);
}

// ---------------------------------------------------------------------------
// 2-term fp16 GEMM: C[m,n] ~= sum_k Ah[m,k]*(Bh[n,k]+Bl[n,k]) + bias[n]
// 128x128 CTA tile, BK=32, cp.async double buffer, 8 warps (64x32 tiles).
// sel 0: Q (scaled log2e/8, fp16 hi only); 1: K split; 2: V split; -1: f32.
// ---------------------------------------------------------------------------
__global__ __launch_bounds__(256, 2) void gemm_2t(
    const half* __restrict__ A, const half* __restrict__ Bh,
    const half* __restrict__ Bl, const float* __restrict__ bias,
    float* __restrict__ Cout, int sel)
{
    extern __shared__ half smg[];
    const int t    = threadIdx.x;
    const int warp = t >> 5;
    const int lane = t & 31;
    const int row0 = blockIdx.x * 128;
    const int col0 = blockIdx.y * 128;
    const int wm   = (warp >> 2) * 64;
    const int wn   = (warp & 3) * 32;

    float acc[4][4][4];
#pragma unroll
    for (int mi = 0; mi < 4; mi++)
#pragma unroll
        for (int ni = 0; ni < 4; ni++)
#pragma unroll
            for (int k = 0; k < 4; k++) acc[mi][ni][k] = 0.f;

    const uint32_t sbase = smem_u32(smg);
    const int lr = t >> 1;
    const int lh = (t & 1) * 16;
    const half* pA = A  + (size_t)(row0 + lr) * EE + lh;
    const half* pB = Bh + (size_t)(col0 + lr) * EE + lh;
    const half* pM = Bl + (size_t)(col0 + lr) * EE + lh;
    const uint32_t drow = (uint32_t)(lr * GSTR + lh) * 2;

    auto load_stage = [&](int c, int s) {
        const uint32_t sb = sbase + (uint32_t)(s * 3 * GS) * 2 + drow;
        const int ko = c * 32;
        cpa16(sb,              pA + ko);  cpa16(sb + 16,              pA + ko + 8);
        cpa16(sb + GS*2,       pB + ko);  cpa16(sb + GS*2 + 16,       pB + ko + 8);
        cpa16(sb + 2*GS*2,     pM + ko);  cpa16(sb + 2*GS*2 + 16,     pM + ko + 8);
    };

    load_stage(0, 0);
    CP_COMMIT();

    const int a_row  = lane & 15;
    const int a_half = (lane >> 4) << 3;

    for (int c = 0; c < 32; c++) {
        if (c + 1 < 32) { load_stage(c + 1, (c + 1) & 1); CP_COMMIT(); }
        if (c + 1 < 32) { CP_WAIT1(); } else { CP_WAIT0(); }
        __syncthreads();

        const uint32_t uA  = sbase + (uint32_t)((c & 1) * 3 * GS) * 2;
        const uint32_t uB  = uA + GS * 2;
        const uint32_t uBl = uA + 2 * GS * 2;

#pragma unroll
        for (int ks = 0; ks < 2; ks++) {
            const int kk = ks * 16;
            uint32_t bH[4][2], bL[4][2];
#pragma unroll
            for (int u = 0; u < 2; u++) {
                const uint32_t bo = (uint32_t)((wn + u*16 + a_row) * GSTR + kk + a_half) * 2;
                uint32_t r0, r1, r2, r3;
                ldsm_x4(r0, r1, r2, r3, uB + bo);
                bH[2*u][0] = r0; bH[2*u][1] = r2; bH[2*u+1][0] = r1; bH[2*u+1][1] = r3;
                ldsm_x4(r0, r1, r2, r3, uBl + bo);
                bL[2*u][0] = r0; bL[2*u][1] = r2; bL[2*u+1][0] = r1; bL[2*u+1][1] = r3;
            }
#pragma unroll
            for (int mi = 0; mi < 4; mi++) {
                const uint32_t ao = (uint32_t)((wm + mi*16 + a_row) * GSTR + kk + a_half) * 2;
                uint32_t aH[4];
                ldsm_x4(aH[0], aH[1], aH[2], aH[3], uA + ao);
#pragma unroll
                for (int ni = 0; ni < 4; ni++) {
                    mma_f16(acc[mi][ni], aH, bH[ni][0], bH[ni][1]);
                    mma_f16(acc[mi][ni], aH, bL[ni][0], bL[ni][1]);
                }
            }
        }
        __syncthreads();
    }

    // ---- epilogue ----
    const int gr = lane >> 2;
    const int gc = (lane & 3) * 2;
    const float qs = (sel == 0) ? (0.125f * LOG2E) : 1.f;
#pragma unroll
    for (int mi = 0; mi < 4; mi++) {
#pragma unroll
        for (int ni = 0; ni < 4; ni++) {
#pragma unroll
            for (int half_ = 0; half_ < 2; half_++) {
                const int m = row0 + wm + mi*16 + gr + half_*8;
                const int n = col0 + wn + ni*8 + gc;
                float v0 = acc[mi][ni][half_*2+0] + bias[n];
                float v1 = acc[mi][ni][half_*2+1] + bias[n+1];
                if (sel < 0) {
                    *(float2*)&Cout[(size_t)m * EE + n] = make_float2(v0, v1);
                } else {
                    const int b = m >> 11, s = m & 2047;
                    const int hh = n >> 6, d = n & 63;
                    const size_t idx = ((((size_t)b*HH + hh)*SS + s)*DD + d) >> 1;
                    if (sel == 0) {
                        ((uint32_t*)g_Q)[idx] = pack_h2(v0 * qs, v1 * qs);
                    } else {
                        uint32_t hp, lp;
                        split2h(v0, v1, hp, lp);
                        if (sel == 1) { ((uint32_t*)g_Kh)[idx] = hp; ((uint32_t*)g_Kl)[idx] = lp; }
                        else          { ((uint32_t*)g_Vh)[idx] = hp; ((uint32_t*)g_Vl)[idx] = lp; }
                    }
                }
            }
        }
    }
}

// ---------------------------------------------------------------------------
// Tensor-core flash attention (2-term fp16, base-2 online softmax).
// grid (S/128, B*H), 256 threads (8 warps x 16 query rows), 2 CTAs/SM.
// Q fp16 in smem; K/V hi+lo double-buffered. Writes fp16 att to g_att [M,E].
// ---------------------------------------------------------------------------
__global__ __launch_bounds__(256, 2) void attn_mma()
{
    extern __shared__ half sma[];
    const int t    = threadIdx.x;
    const int warp = t >> 5;
    const int lane = t & 31;
    const int bh   = blockIdx.y;
    const int q0   = blockIdx.x * 128;
    const int b    = bh >> 4;
    const int h    = bh & 15;

    const uint32_t sbase = smem_u32(sma);
    const uint32_t uQ = sbase;
    const size_t bhoff = (size_t)bh * SS * DD;

    // ---- Q tile -> smem via cp.async (2 threads/row, 32 halves each) ----
    {
        const int qrow = t >> 1;
        const int qch  = (t & 1) * 32;
        const size_t src = bhoff + (size_t)(q0 + qrow)*DD + qch;
        const uint32_t dst = sbase + (uint32_t)(qrow * KSTR + qch) * 2;
#pragma unroll
        for (int c = 0; c < 32; c += 8)
            cpa16(dst + c*2, g_Q + src + c);
    }

    // ---- K/V tile cp.async loaders (full-row coverage) ----
    const int lrow = t >> 2;
    const int lchk = (t & 3) * 16;
    const uint32_t ddst = (uint32_t)(lrow * KSTR + lchk) * 2;
    auto load_kv = [&](int kb, int s) {
        const size_t src = bhoff + (size_t)(kb*64 + lrow)*DD + lchk;
        const uint32_t sb = sbase + (uint32_t)(QTILE + s * 4 * ATILE) * 2 + ddst;
        cpa16(sb,                 g_Kh + src);
        cpa16(sb + 16,            g_Kh + src + 8);
        cpa16(sb + ATILE*2,       g_Kl + src);
        cpa16(sb + ATILE*2 + 16,  g_Kl + src + 8);
        cpa16(sb + 2*ATILE*2,       g_Vh + src);
        cpa16(sb + 2*ATILE*2 + 16,  g_Vh + src + 8);
        cpa16(sb + 3*ATILE*2,       g_Vl + src);
        cpa16(sb + 3*ATILE*2 + 16,  g_Vl + src + 8);
    };

    float m0 = -1e30f, m1 = -1e30f, l0 = 0.f, l1 = 0.f;
    float oc[8][4];
#pragma unroll
    for (int ni = 0; ni < 8; ni++)
#pragma unroll
        for (int k = 0; k < 4; k++) oc[ni][k] = 0.f;

    load_kv(0, 0);
    CP_COMMIT();

    const int a_row  = lane & 15;
    const int a_half = (lane >> 4) << 3;
    const int g      = lane >> 3;
    const int t_row  = (g & 1)*8 + (lane & 7);
    const int t_col  = (g >> 1)*8;

    for (int kb = 0; kb < SS/64; kb++) {
        if (kb + 1 < SS/64) { load_kv(kb + 1, (kb + 1) & 1); CP_COMMIT(); }
        if (kb + 1 < SS/64) { CP_WAIT1(); } else { CP_WAIT0(); }
        __syncthreads();

        const uint32_t uKh = sbase + (uint32_t)(QTILE + (kb & 1) * 4 * ATILE) * 2;
        const uint32_t uKl = uKh + ATILE*2;
        const uint32_t uVh = uKh + 2*ATILE*2;
        const uint32_t uVl = uKh + 3*ATILE*2;

        // ---- S = Q K^T (log2 domain): qh*(kh + kl) ----
        float sc[8][4];
#pragma unroll
        for (int ni = 0; ni < 8; ni++)
#pragma unroll
            for (int k = 0; k < 4; k++) sc[ni][k] = 0.f;

#pragma unroll
        for (int ks = 0; ks < 4; ks++) {
            const int kk = ks * 16;
            const uint32_t qo = (uint32_t)((warp*16 + a_row) * KSTR + kk + a_half) * 2;
            uint32_t qh[4];
            ldsm_x4(qh[0], qh[1], qh[2], qh[3], uQ + qo);
#pragma unroll
            for (int u = 0; u < 4; u++) {
                const uint32_t bo = (uint32_t)((u*16 + a_row) * KSTR + kk + a_half) * 2;
                uint32_t r0, r1, r2, r3, s0, s1, s2, s3;
                ldsm_x4(r0, r1, r2, r3, uKh + bo);
                ldsm_x4(s0, s1, s2, s3, uKl + bo);
                mma_f16(sc[2*u],   qh, r0, r2);
                mma_f16(sc[2*u],   qh, s0, s2);
                mma_f16(sc[2*u+1], qh, r1, r3);
                mma_f16(sc[2*u+1], qh, s1, s3);
            }
        }

        // ---- base-2 online softmax ----
        float mx0 = -1e30f, mx1 = -1e30f;
#pragma unroll
        for (int ni = 0; ni < 8; ni++) {
            mx0 = fmaxf(mx0, fmaxf(sc[ni][0], sc[ni][1]));
            mx1 = fmaxf(mx1, fmaxf(sc[ni][2], sc[ni][3]));
        }
        mx0 = fmaxf(mx0, __shfl_xor_sync(0xffffffffu, mx0, 1));
        mx0 = fmaxf(mx0, __shfl_xor_sync(0xffffffffu, mx0, 2));
        mx1 = fmaxf(mx1, __shfl_xor_sync(0xffffffffu, mx1, 1));
        mx1 = fmaxf(mx1, __shfl_xor_sync(0xffffffffu, mx1, 2));
        const float mn0 = fmaxf(m0, mx0), mn1 = fmaxf(m1, mx1);
        const float al0 = ex2(m0 - mn0), al1 = ex2(m1 - mn1);
        float s0 = 0.f, s1 = 0.f;
#pragma unroll
        for (int ni = 0; ni < 8; ni++) {
            sc[ni][0] = ex2(sc[ni][0] - mn0); s0 += sc[ni][0];
            sc[ni][1] = ex2(sc[ni][1] - mn0); s0 += sc[ni][1];
            sc[ni][2] = ex2(sc[ni][2] - mn1); s1 += sc[ni][2];
            sc[ni][3] = ex2(sc[ni][3] - mn1); s1 += sc[ni][3];
        }
        s0 += __shfl_xor_sync(0xffffffffu, s0, 1);
        s0 += __shfl_xor_sync(0xffffffffu, s0, 2);
        s1 += __shfl_xor_sync(0xffffffffu, s1, 1);
        s1 += __shfl_xor_sync(0xffffffffu, s1, 2);
        l0 = l0 * al0 + s0;  l1 = l1 * al1 + s1;
        m0 = mn0;            m1 = mn1;
#pragma unroll
        for (int ni = 0; ni < 8; ni++) {
            oc[ni][0] *= al0; oc[ni][1] *= al0;
            oc[ni][2] *= al1; oc[ni][3] *= al1;
        }

        // ---- O += P (V hi + V lo), P packed fp16 (no split) ----
#pragma unroll
        for (int ks = 0; ks < 4; ks++) {
            uint32_t ph[4];
            ph[0] = pack_h2(sc[2*ks][0],   sc[2*ks][1]);
            ph[1] = pack_h2(sc[2*ks][2],   sc[2*ks][3]);
            ph[2] = pack_h2(sc[2*ks+1][0], sc[2*ks+1][1]);
            ph[3] = pack_h2(sc[2*ks+1][2], sc[2*ks+1][3]);
            const int keyr = ks*16 + t_row;
#pragma unroll
            for (int p = 0; p < 4; p++) {
                const uint32_t vo = (uint32_t)(keyr * KSTR + 16*p + t_col) * 2;
                uint32_t v0, v1, v2, v3, w0, w1, w2, w3;
                ldsm_x4t(v0, v1, v2, v3, uVh + vo);
                ldsm_x4t(w0, w1, w2, w3, uVl + vo);
                mma_f16(oc[2*p],   ph, v0, v1);
                mma_f16(oc[2*p],   ph, w0, w1);
                mma_f16(oc[2*p+1], ph, v2, v3);
                mma_f16(oc[2*p+1], ph, w2, w3);
            }
        }
        __syncthreads();
    }

    // ---- epilogue: normalize, pack fp16, write g_att [M,E] ----
    const float inv0 = 1.f / l0, inv1 = 1.f / l1;
    const int r0row = q0 + warp*16 + (lane >> 2);
#pragma unroll
    for (int ni = 0; ni < 8; ni++) {
        const int d = ni*8 + (lane & 3)*2;
        const size_t col = (size_t)h*DD + d;
        size_t idx = (((size_t)b*SS + r0row)*EE + col) >> 1;
        ((uint32_t*)g_att)[idx] = pack_h2(oc[ni][0]*inv0, oc[ni][1]*inv0);
        idx = (((size_t)b*SS + r0row + 8)*EE + col) >> 1;
        ((uint32_t*)g_att)[idx] = pack_h2(oc[ni][2]*inv1, oc[ni][3]*inv1);
    }
}

// ---------------------------------------------------------------------------
extern "C" void kernel_launch(void* const* d_in, const int* in_sizes, int n_in,
                              void* d_out, int out_size)
{
    const float* x  = (const float*)d_in[0];
    const float* Wq = (const float*)d_in[1];
    const float* bq = (const float*)d_in[2];
    const float* Wk = (const float*)d_in[3];
    const float* bk = (const float*)d_in[4];
    const float* Wv = (const float*)d_in[5];
    const float* bv = (const float*)d_in[6];
    const float* Wo = (const float*)d_in[7];
    const float* bo = (const float*)d_in[8];
    float* out = (float*)d_out;

    half *xp, *ap;
    half *wqh, *wql, *wkh, *wkl, *wvh, *wvl, *woh, *wol;
    cudaGetSymbolAddress((void**)&xp,  g_x);   cudaGetSymbolAddress((void**)&ap,  g_att);
    cudaGetSymbolAddress((void**)&wqh, g_wqh); cudaGetSymbolAddress((void**)&wql, g_wql);
    cudaGetSymbolAddress((void**)&wkh, g_wkh); cudaGetSymbolAddress((void**)&wkl, g_wkl);
    cudaGetSymbolAddress((void**)&wvh, g_wvh); cudaGetSymbolAddress((void**)&wvl, g_wvl);
    cudaGetSymbolAddress((void**)&woh, g_woh); cudaGetSymbolAddress((void**)&wol, g_wol);

    conv_h <<<(MM*EE/4 + 255)/256, 256>>>(x,  xp,  MM*EE/4);
    conv_hl<<<(EE*EE/4 + 255)/256, 256>>>(Wq, wqh, wql, EE*EE/4);
    conv_hl<<<(EE*EE/4 + 255)/256, 256>>>(Wk, wkh, wkl, EE*EE/4);
    conv_hl<<<(EE*EE/4 + 255)/256, 256>>>(Wv, wvh, wvl, EE*EE/4);
    conv_hl<<<(EE*EE/4 + 255)/256, 256>>>(Wo, woh, wol, EE*EE/4);

    const int gsmem = 2 * 3 * GS * 2;                 // 61,440 B
    const int asmem = (QTILE + 2 * 4 * ATILE) * 2;    // 92,160 B
    cudaFuncSetAttribute(gemm_2t,  cudaFuncAttributeMaxDynamicSharedMemorySize, gsmem);
    cudaFuncSetAttribute(attn_mma, cudaFuncAttributeMaxDynamicSharedMemorySize, asmem);

    dim3 gp(MM/128, EE/128);
    gemm_2t<<<gp, 256, gsmem>>>(xp, wqh, wql, bq, nullptr, 0);
    gemm_2t<<<gp, 256, gsmem>>>(xp, wkh, wkl, bk, nullptr, 1);
    gemm_2t<<<gp, 256, gsmem>>>(xp, wvh, wvl, bv, nullptr, 2);

    attn_mma<<<dim3(SS/128, BB*HH), 256, asmem>>>();

    gemm_2t<<<gp, 256, gsmem>>>(ap, woh, wol, bo, out, -1);
}

// round 11
// speedup vs baseline: 6.8543x; 1.1888x over previous
#include <cuda_runtime.h>
#include <cuda_fp16.h>
#include <cstdint>

#define BB 2
#define SS 2048
#define EE 1024
#define HH 16
#define DD 64
#define MM (BB*SS)
#define GSTR 40            // gemm smem row stride (halves)
#define GS (128*GSTR)      // halves per gemm tile array
#define KSTR 72            // attn smem row stride (halves)
#define ATILE (64*KSTR)    // halves per attn K/V tile array
#define QTILE (128*KSTR)   // halves per attn Q tile array
#define LOG2E 1.4426950408889634f

// ---------------- scratch (device globals: allocation-free rule) ------------
__device__ half g_x[MM*EE];                 // x, fp16 (A-side)
__device__ half g_att[MM*EE];               // attention out, fp16 (A-side)
__device__ half g_wqh[EE*EE], g_wql[EE*EE];
__device__ half g_wkh[EE*EE], g_wkl[EE*EE];
__device__ half g_wvh[EE*EE], g_wvl[EE*EE];
__device__ half g_woh[EE*EE], g_wol[EE*EE];
__device__ half g_Q[BB*HH*SS*DD];           // pre-scaled by log2e/8
__device__ half g_K[BB*HH*SS*DD];
__device__ half g_V[BB*HH*SS*DD];

// ---------------- helpers ---------------------------------------------------
__device__ __forceinline__ uint32_t smem_u32(const void* p) {
    uint32_t a;
    asm("{ .reg .u64 t; cvta.to.shared.u64 t, %1; cvt.u32.u64 %0, t; }" : "=r"(a) : "l"(p));
    return a;
}
__device__ __forceinline__ void ldsm_x4(uint32_t& r0, uint32_t& r1, uint32_t& r2,
                                        uint32_t& r3, uint32_t addr) {
    asm volatile("ldmatrix.sync.aligned.m8n8.x4.shared.b16 {%0,%1,%2,%3}, [%4];"
                 : "=r"(r0), "=r"(r1), "=r"(r2), "=r"(r3) : "r"(addr));
}
__device__ __forceinline__ void ldsm_x4t(uint32_t& r0, uint32_t& r1, uint32_t& r2,
                                         uint32_t& r3, uint32_t addr) {
    asm volatile("ldmatrix.sync.aligned.m8n8.x4.trans.shared.b16 {%0,%1,%2,%3}, [%4];"
                 : "=r"(r0), "=r"(r1), "=r"(r2), "=r"(r3) : "r"(addr));
}
__device__ __forceinline__ void mma_f16(float* c, const uint32_t* a,
                                        uint32_t b0, uint32_t b1) {
    asm volatile(
        "mma.sync.aligned.m16n8k16.row.col.f32.f16.f16.f32 "
        "{%0,%1,%2,%3}, {%4,%5,%6,%7}, {%8,%9}, {%0,%1,%2,%3};"
        : "+f"(c[0]), "+f"(c[1]), "+f"(c[2]), "+f"(c[3])
        : "r"(a[0]), "r"(a[1]), "r"(a[2]), "r"(a[3]), "r"(b0), "r"(b1));
}
__device__ __forceinline__ void cpa16(uint32_t dst, const void* src) {
    asm volatile("cp.async.cg.shared.global [%0], [%1], 16;" :: "r"(dst), "l"(src));
}
#define CP_COMMIT() asm volatile("cp.async.commit_group;" ::: "memory")
#define CP_WAIT1()  asm volatile("cp.async.wait_group 1;" ::: "memory")
#define CP_WAIT0()  asm volatile("cp.async.wait_group 0;" ::: "memory")

__device__ __forceinline__ float ex2(float x) {
    float r;
    asm("ex2.approx.f32 %0, %1;" : "=f"(r) : "f"(x));
    return r;
}
__device__ __forceinline__ uint32_t pack_h2(float a, float b) {
    __half2 h = __floats2half2_rn(a, b);
    return *(uint32_t*)&h;
}
__device__ __forceinline__ void split2h(float a, float b, uint32_t& hp, uint32_t& lp) {
    __half2 h = __floats2half2_rn(a, b);
    float2 f = __half22float2(h);
    hp = *(uint32_t*)&h;
    __half2 l = __floats2half2_rn(a - f.x, b - f.y);
    lp = *(uint32_t*)&l;
}

// ---------------- conversion kernels ----------------------------------------
__global__ __launch_bounds__(256) void conv_h(
    const float* __restrict__ in, half* __restrict__ out, int n4)
{
    int i = blockIdx.x * blockDim.x + threadIdx.x;
    if (i >= n4) return;
    float4 v = ((const float4*)in)[i];
    ((uint2*)out)[i] = make_uint2(pack_h2(v.x, v.y), pack_h2(v.z, v.w));
}
__global__ __launch_bounds__(256) void conv_hl(
    const float* __restrict__ in, half* __restrict__ hi, half* __restrict__ lo, int n4)
{
    int i = blockIdx.x * blockDim.x + threadIdx.x;
    if (i >= n4) return;
    float4 v = ((const float4*)in)[i];
    uint32_t h0, l0, h1, l1;
    split2h(v.x, v.y, h0, l0);
    split2h(v.z, v.w, h1, l1);
    ((uint2*)hi)[i] = make_uint2(h0, h1);
    ((uint2*)lo)[i] = make_uint2(l0, l1);
}

// ---------------------------------------------------------------------------
// 2-term fp16 GEMM: C[m,n] ~= sum_k A[m,k]*(Bh[n,k]+Bl[n,k]) + bias[n]
// 128x128 CTA tile, BK=32, cp.async double buffer, 8 warps (64x32 tiles).
// sel 0/1/2: fp16 Q/K/V [B,H,S,D] (Q scaled log2e/8); -1: f32 row-major.
// ---------------------------------------------------------------------------
__global__ __launch_bounds__(256, 2) void gemm_2t(
    const half* __restrict__ A, const half* __restrict__ Bh,
    const half* __restrict__ Bl, const float* __restrict__ bias,
    float* __restrict__ Cout, int sel)
{
    extern __shared__ half smg[];
    const int t    = threadIdx.x;
    const int warp = t >> 5;
    const int lane = t & 31;
    const int row0 = blockIdx.x * 128;
    const int col0 = blockIdx.y * 128;
    const int wm   = (warp >> 2) * 64;
    const int wn   = (warp & 3) * 32;

    float acc[4][4][4];
#pragma unroll
    for (int mi = 0; mi < 4; mi++)
#pragma unroll
        for (int ni = 0; ni < 4; ni++)
#pragma unroll
            for (int k = 0; k < 4; k++) acc[mi][ni][k] = 0.f;

    const uint32_t sbase = smem_u32(smg);
    const int lr = t >> 1;
    const int lh = (t & 1) * 16;
    const half* pA = A  + (size_t)(row0 + lr) * EE + lh;
    const half* pB = Bh + (size_t)(col0 + lr) * EE + lh;
    const half* pM = Bl + (size_t)(col0 + lr) * EE + lh;
    const uint32_t drow = (uint32_t)(lr * GSTR + lh) * 2;

    auto load_stage = [&](int c, int s) {
        const uint32_t sb = sbase + (uint32_t)(s * 3 * GS) * 2 + drow;
        const int ko = c * 32;
        cpa16(sb,              pA + ko);  cpa16(sb + 16,              pA + ko + 8);
        cpa16(sb + GS*2,       pB + ko);  cpa16(sb + GS*2 + 16,       pB + ko + 8);
        cpa16(sb + 2*GS*2,     pM + ko);  cpa16(sb + 2*GS*2 + 16,     pM + ko + 8);
    };

    load_stage(0, 0);
    CP_COMMIT();

    const int a_row  = lane & 15;
    const int a_half = (lane >> 4) << 3;

    for (int c = 0; c < 32; c++) {
        if (c + 1 < 32) { load_stage(c + 1, (c + 1) & 1); CP_COMMIT(); }
        if (c + 1 < 32) { CP_WAIT1(); } else { CP_WAIT0(); }
        __syncthreads();

        const uint32_t uA  = sbase + (uint32_t)((c & 1) * 3 * GS) * 2;
        const uint32_t uB  = uA + GS * 2;
        const uint32_t uBl = uA + 2 * GS * 2;

#pragma unroll
        for (int ks = 0; ks < 2; ks++) {
            const int kk = ks * 16;
            uint32_t bH[4][2], bL[4][2];
#pragma unroll
            for (int u = 0; u < 2; u++) {
                const uint32_t bo = (uint32_t)((wn + u*16 + a_row) * GSTR + kk + a_half) * 2;
                uint32_t r0, r1, r2, r3;
                ldsm_x4(r0, r1, r2, r3, uB + bo);
                bH[2*u][0] = r0; bH[2*u][1] = r2; bH[2*u+1][0] = r1; bH[2*u+1][1] = r3;
                ldsm_x4(r0, r1, r2, r3, uBl + bo);
                bL[2*u][0] = r0; bL[2*u][1] = r2; bL[2*u+1][0] = r1; bL[2*u+1][1] = r3;
            }
#pragma unroll
            for (int mi = 0; mi < 4; mi++) {
                const uint32_t ao = (uint32_t)((wm + mi*16 + a_row) * GSTR + kk + a_half) * 2;
                uint32_t aH[4];
                ldsm_x4(aH[0], aH[1], aH[2], aH[3], uA + ao);
#pragma unroll
                for (int ni = 0; ni < 4; ni++) {
                    mma_f16(acc[mi][ni], aH, bH[ni][0], bH[ni][1]);
                    mma_f16(acc[mi][ni], aH, bL[ni][0], bL[ni][1]);
                }
            }
        }
        __syncthreads();
    }

    // ---- epilogue ----
    const int gr = lane >> 2;
    const int gc = (lane & 3) * 2;
    const float qs = (sel == 0) ? (0.125f * LOG2E) : 1.f;
#pragma unroll
    for (int mi = 0; mi < 4; mi++) {
#pragma unroll
        for (int ni = 0; ni < 4; ni++) {
#pragma unroll
            for (int half_ = 0; half_ < 2; half_++) {
                const int m = row0 + wm + mi*16 + gr + half_*8;
                const int n = col0 + wn + ni*8 + gc;
                float v0 = acc[mi][ni][half_*2+0] + bias[n];
                float v1 = acc[mi][ni][half_*2+1] + bias[n+1];
                if (sel < 0) {
                    *(float2*)&Cout[(size_t)m * EE + n] = make_float2(v0, v1);
                } else {
                    const int b = m >> 11, s = m & 2047;
                    const int hh = n >> 6, d = n & 63;
                    const size_t idx = ((((size_t)b*HH + hh)*SS + s)*DD + d) >> 1;
                    half* outp = (sel == 0) ? g_Q : (sel == 1) ? g_K : g_V;
                    ((uint32_t*)outp)[idx] = pack_h2(v0 * qs, v1 * qs);
                }
            }
        }
    }
}

// ---------------------------------------------------------------------------
// Tensor-core flash attention (pure fp16 MMAs, base-2 online softmax).
// grid (S/128, B*H), 256 threads (8 warps x 16 query rows), 2 CTAs/SM.
// Q fp16 in smem; K/V fp16 double-buffered. Writes fp16 att to g_att [M,E].
// ---------------------------------------------------------------------------
__global__ __launch_bounds__(256, 2) void attn_mma()
{
    extern __shared__ half sma[];
    const int t    = threadIdx.x;
    const int warp = t >> 5;
    const int lane = t & 31;
    const int bh   = blockIdx.y;
    const int q0   = blockIdx.x * 128;
    const int b    = bh >> 4;
    const int h    = bh & 15;

    const uint32_t sbase = smem_u32(sma);
    const uint32_t uQ = sbase;
    const size_t bhoff = (size_t)bh * SS * DD;

    // ---- Q tile -> smem via cp.async (2 threads/row, 32 halves each) ----
    {
        const int qrow = t >> 1;
        const int qch  = (t & 1) * 32;
        const size_t src = bhoff + (size_t)(q0 + qrow)*DD + qch;
        const uint32_t dst = sbase + (uint32_t)(qrow * KSTR + qch) * 2;
#pragma unroll
        for (int c = 0; c < 32; c += 8)
            cpa16(dst + c*2, g_Q + src + c);
    }

    // ---- K/V tile cp.async loaders (full-row coverage, 2 arrays) ----
    const int lrow = t >> 2;
    const int lchk = (t & 3) * 16;
    const uint32_t ddst = (uint32_t)(lrow * KSTR + lchk) * 2;
    auto load_kv = [&](int kb, int s) {
        const size_t src = bhoff + (size_t)(kb*64 + lrow)*DD + lchk;
        const uint32_t sb = sbase + (uint32_t)(QTILE + s * 2 * ATILE) * 2 + ddst;
        cpa16(sb,                 g_K + src);
        cpa16(sb + 16,            g_K + src + 8);
        cpa16(sb + ATILE*2,       g_V + src);
        cpa16(sb + ATILE*2 + 16,  g_V + src + 8);
    };

    float m0 = -1e30f, m1 = -1e30f, l0 = 0.f, l1 = 0.f;
    float oc[8][4];
#pragma unroll
    for (int ni = 0; ni < 8; ni++)
#pragma unroll
        for (int k = 0; k < 4; k++) oc[ni][k] = 0.f;

    load_kv(0, 0);
    CP_COMMIT();

    const int a_row  = lane & 15;
    const int a_half = (lane >> 4) << 3;
    const int g      = lane >> 3;
    const int t_row  = (g & 1)*8 + (lane & 7);
    const int t_col  = (g >> 1)*8;

    for (int kb = 0; kb < SS/64; kb++) {
        if (kb + 1 < SS/64) { load_kv(kb + 1, (kb + 1) & 1); CP_COMMIT(); }
        if (kb + 1 < SS/64) { CP_WAIT1(); } else { CP_WAIT0(); }
        __syncthreads();

        const uint32_t uK = sbase + (uint32_t)(QTILE + (kb & 1) * 2 * ATILE) * 2;
        const uint32_t uV = uK + ATILE*2;

        // ---- S = Q K^T (log2 domain) ----
        float sc[8][4];
#pragma unroll
        for (int ni = 0; ni < 8; ni++)
#pragma unroll
            for (int k = 0; k < 4; k++) sc[ni][k] = 0.f;

#pragma unroll
        for (int ks = 0; ks < 4; ks++) {
            const int kk = ks * 16;
            const uint32_t qo = (uint32_t)((warp*16 + a_row) * KSTR + kk + a_half) * 2;
            uint32_t qh[4];
            ldsm_x4(qh[0], qh[1], qh[2], qh[3], uQ + qo);
#pragma unroll
            for (int u = 0; u < 4; u++) {
                const uint32_t bo = (uint32_t)((u*16 + a_row) * KSTR + kk + a_half) * 2;
                uint32_t r0, r1, r2, r3;
                ldsm_x4(r0, r1, r2, r3, uK + bo);
                mma_f16(sc[2*u],   qh, r0, r2);
                mma_f16(sc[2*u+1], qh, r1, r3);
            }
        }

        // ---- base-2 online softmax ----
        float mx0 = -1e30f, mx1 = -1e30f;
#pragma unroll
        for (int ni = 0; ni < 8; ni++) {
            mx0 = fmaxf(mx0, fmaxf(sc[ni][0], sc[ni][1]));
            mx1 = fmaxf(mx1, fmaxf(sc[ni][2], sc[ni][3]));
        }
        mx0 = fmaxf(mx0, __shfl_xor_sync(0xffffffffu, mx0, 1));
        mx0 = fmaxf(mx0, __shfl_xor_sync(0xffffffffu, mx0, 2));
        mx1 = fmaxf(mx1, __shfl_xor_sync(0xffffffffu, mx1, 1));
        mx1 = fmaxf(mx1, __shfl_xor_sync(0xffffffffu, mx1, 2));
        const float mn0 = fmaxf(m0, mx0), mn1 = fmaxf(m1, mx1);
        const float al0 = ex2(m0 - mn0), al1 = ex2(m1 - mn1);
        float s0 = 0.f, s1 = 0.f;
#pragma unroll
        for (int ni = 0; ni < 8; ni++) {
            sc[ni][0] = ex2(sc[ni][0] - mn0); s0 += sc[ni][0];
            sc[ni][1] = ex2(sc[ni][1] - mn0); s0 += sc[ni][1];
            sc[ni][2] = ex2(sc[ni][2] - mn1); s1 += sc[ni][2];
            sc[ni][3] = ex2(sc[ni][3] - mn1); s1 += sc[ni][3];
        }
        s0 += __shfl_xor_sync(0xffffffffu, s0, 1);
        s0 += __shfl_xor_sync(0xffffffffu, s0, 2);
        s1 += __shfl_xor_sync(0xffffffffu, s1, 1);
        s1 += __shfl_xor_sync(0xffffffffu, s1, 2);
        l0 = l0 * al0 + s0;  l1 = l1 * al1 + s1;
        m0 = mn0;            m1 = mn1;
#pragma unroll
        for (int ni = 0; ni < 8; ni++) {
            oc[ni][0] *= al0; oc[ni][1] *= al0;
            oc[ni][2] *= al1; oc[ni][3] *= al1;
        }

        // ---- O += P V, P packed fp16 ----
#pragma unroll
        for (int ks = 0; ks < 4; ks++) {
            uint32_t ph[4];
            ph[0] = pack_h2(sc[2*ks][0],   sc[2*ks][1]);
            ph[1] = pack_h2(sc[2*ks][2],   sc[2*ks][3]);
            ph[2] = pack_h2(sc[2*ks+1][0], sc[2*ks+1][1]);
            ph[3] = pack_h2(sc[2*ks+1][2], sc[2*ks+1][3]);
            const int keyr = ks*16 + t_row;
#pragma unroll
            for (int p = 0; p < 4; p++) {
                const uint32_t vo = (uint32_t)(keyr * KSTR + 16*p + t_col) * 2;
                uint32_t v0, v1, v2, v3;
                ldsm_x4t(v0, v1, v2, v3, uV + vo);
                mma_f16(oc[2*p],   ph, v0, v1);
                mma_f16(oc[2*p+1], ph, v2, v3);
            }
        }
        __syncthreads();
    }

    // ---- epilogue: normalize, pack fp16, write g_att [M,E] ----
    const float inv0 = 1.f / l0, inv1 = 1.f / l1;
    const int r0row = q0 + warp*16 + (lane >> 2);
#pragma unroll
    for (int ni = 0; ni < 8; ni++) {
        const int d = ni*8 + (lane & 3)*2;
        const size_t col = (size_t)h*DD + d;
        size_t idx = (((size_t)b*SS + r0row)*EE + col) >> 1;
        ((uint32_t*)g_att)[idx] = pack_h2(oc[ni][0]*inv0, oc[ni][1]*inv0);
        idx = (((size_t)b*SS + r0row + 8)*EE + col) >> 1;
        ((uint32_t*)g_att)[idx] = pack_h2(oc[ni][2]*inv1, oc[ni][3]*inv1);
    }
}

// ---------------------------------------------------------------------------
extern "C" void kernel_launch(void* const* d_in, const int* in_sizes, int n_in,
                              void* d_out, int out_size)
{
    const float* x  = (const float*)d_in[0];
    const float* Wq = (const float*)d_in[1];
    const float* bq = (const float*)d_in[2];
    const float* Wk = (const float*)d_in[3];
    const float* bk = (const float*)d_in[4];
    const float* Wv = (const float*)d_in[5];
    const float* bv = (const float*)d_in[6];
    const float* Wo = (const float*)d_in[7];
    const float* bo = (const float*)d_in[8];
    float* out = (float*)d_out;

    half *xp, *ap;
    half *wqh, *wql, *wkh, *wkl, *wvh, *wvl, *woh, *wol;
    cudaGetSymbolAddress((void**)&xp,  g_x);   cudaGetSymbolAddress((void**)&ap,  g_att);
    cudaGetSymbolAddress((void**)&wqh, g_wqh); cudaGetSymbolAddress((void**)&wql, g_wql);
    cudaGetSymbolAddress((void**)&wkh, g_wkh); cudaGetSymbolAddress((void**)&wkl, g_wkl);
    cudaGetSymbolAddress((void**)&wvh, g_wvh); cudaGetSymbolAddress((void**)&wvl, g_wvl);
    cudaGetSymbolAddress((void**)&woh, g_woh); cudaGetSymbolAddress((void**)&wol, g_wol);

    conv_h <<<(MM*EE/4 + 255)/256, 256>>>(x,  xp,  MM*EE/4);
    conv_hl<<<(EE*EE/4 + 255)/256, 256>>>(Wq, wqh, wql, EE*EE/4);
    conv_hl<<<(EE*EE/4 + 255)/256, 256>>>(Wk, wkh, wkl, EE*EE/4);
    conv_hl<<<(EE*EE/4 + 255)/256, 256>>>(Wv, wvh, wvl, EE*EE/4);
    conv_hl<<<(EE*EE/4 + 255)/256, 256>>>(Wo, woh, wol, EE*EE/4);

    const int gsmem = 2 * 3 * GS * 2;                 // 61,440 B
    const int asmem = (QTILE + 2 * 2 * ATILE) * 2;    // 55,296 B
    cudaFuncSetAttribute(gemm_2t,  cudaFuncAttributeMaxDynamicSharedMemorySize, gsmem);
    cudaFuncSetAttribute(attn_mma, cudaFuncAttributeMaxDynamicSharedMemorySize, asmem);

    dim3 gp(MM/128, EE/128);
    gemm_2t<<<gp, 256, gsmem>>>(xp, wqh, wql, bq, nullptr, 0);
    gemm_2t<<<gp, 256, gsmem>>>(xp, wkh, wkl, bk, nullptr, 1);
    gemm_2t<<<gp, 256, gsmem>>>(xp, wvh, wvl, bv, nullptr, 2);

    attn_mma<<<dim3(SS/128, BB*HH), 256, asmem>>>();

    gemm_2t<<<gp, 256, gsmem>>>(ap, woh, wol, bo, out, -1);
}

// round 13
// speedup vs baseline: 9.2462x; 1.3490x over previous
#include <cuda_runtime.h>
#include <cuda_fp16.h>
#include <cstdint>

#define BB 2
#define SS 2048
#define EE 1024
#define HH 16
#define DD 64
#define MM (BB*SS)
#define GSTR 40            // gemm smem row stride (halves)
#define GS (128*GSTR)      // halves per gemm tile array
#define KSTR 72            // attn smem row stride (halves)
#define ATILE (64*KSTR)    // halves per attn K/V tile array
#define QTILE (128*KSTR)   // halves per attn Q tile array
#define LOG2E 1.4426950408889634f

// ---------------- scratch (device globals: allocation-free rule) ------------
__device__ half g_x[MM*EE];                 // x, fp16
__device__ half g_att[MM*EE];               // attention out, fp16
__device__ half g_wq[EE*EE], g_wk[EE*EE], g_wv[EE*EE], g_wo[EE*EE];
__device__ half g_Q[BB*HH*SS*DD];           // pre-scaled by log2e/8
__device__ half g_K[BB*HH*SS*DD];
__device__ half g_V[BB*HH*SS*DD];

// ---------------- helpers ---------------------------------------------------
__device__ __forceinline__ uint32_t smem_u32(const void* p) {
    uint32_t a;
    asm("{ .reg .u64 t; cvta.to.shared.u64 t, %1; cvt.u32.u64 %0, t; }" : "=r"(a) : "l"(p));
    return a;
}
__device__ __forceinline__ void ldsm_x4(uint32_t& r0, uint32_t& r1, uint32_t& r2,
                                        uint32_t& r3, uint32_t addr) {
    asm volatile("ldmatrix.sync.aligned.m8n8.x4.shared.b16 {%0,%1,%2,%3}, [%4];"
                 : "=r"(r0), "=r"(r1), "=r"(r2), "=r"(r3) : "r"(addr));
}
__device__ __forceinline__ void ldsm_x4t(uint32_t& r0, uint32_t& r1, uint32_t& r2,
                                         uint32_t& r3, uint32_t addr) {
    asm volatile("ldmatrix.sync.aligned.m8n8.x4.trans.shared.b16 {%0,%1,%2,%3}, [%4];"
                 : "=r"(r0), "=r"(r1), "=r"(r2), "=r"(r3) : "r"(addr));
}
__device__ __forceinline__ void mma_f16(float* c, const uint32_t* a,
                                        uint32_t b0, uint32_t b1) {
    asm volatile(
        "mma.sync.aligned.m16n8k16.row.col.f32.f16.f16.f32 "
        "{%0,%1,%2,%3}, {%4,%5,%6,%7}, {%8,%9}, {%0,%1,%2,%3};"
        : "+f"(c[0]), "+f"(c[1]), "+f"(c[2]), "+f"(c[3])
        : "r"(a[0]), "r"(a[1]), "r"(a[2]), "r"(a[3]), "r"(b0), "r"(b1));
}
__device__ __forceinline__ void cpa16(uint32_t dst, const void* src) {
    asm volatile("cp.async.cg.shared.global [%0], [%1], 16;" :: "r"(dst), "l"(src));
}
#define CP_COMMIT() asm volatile("cp.async.commit_group;" ::: "memory")
#define CP_WAIT1()  asm volatile("cp.async.wait_group 1;" ::: "memory")
#define CP_WAIT0()  asm volatile("cp.async.wait_group 0;" ::: "memory")

__device__ __forceinline__ float ex2(float x) {
    float r;
    asm("ex2.approx.f32 %0, %1;" : "=f"(r) : "f"(x));
    return r;
}
__device__ __forceinline__ uint32_t pack_h2(float a, float b) {
    __half2 h = __floats2half2_rn(a, b);
    return *(uint32_t*)&h;
}

// ---------------- fp32 -> fp16 conversion -----------------------------------
__global__ __launch_bounds__(256) void conv_h(
    const float* __restrict__ in, half* __restrict__ out, int n4)
{
    int i = blockIdx.x * blockDim.x + threadIdx.x;
    if (i >= n4) return;
    float4 v = ((const float4*)in)[i];
    ((uint2*)out)[i] = make_uint2(pack_h2(v.x, v.y), pack_h2(v.z, v.w));
}

// ---------------------------------------------------------------------------
// 1-term fp16 GEMM: C[m,n] ~= sum_k A[m,k]*B[n,k] + bias[n]
// 128x128 CTA tile, BK=32, cp.async double buffer, 8 warps (64x32 tiles).
// sel 0/1/2: fp16 Q/K/V [B,H,S,D] (Q scaled log2e/8); -1: f32 row-major.
// ---------------------------------------------------------------------------
__global__ __launch_bounds__(256, 2) void gemm_1t(
    const half* __restrict__ A, const half* __restrict__ B,
    const float* __restrict__ bias, float* __restrict__ Cout, int sel)
{
    extern __shared__ half smg[];
    const int t    = threadIdx.x;
    const int warp = t >> 5;
    const int lane = t & 31;
    const int row0 = blockIdx.x * 128;
    const int col0 = blockIdx.y * 128;
    const int wm   = (warp >> 2) * 64;
    const int wn   = (warp & 3) * 32;

    float acc[4][4][4];
#pragma unroll
    for (int mi = 0; mi < 4; mi++)
#pragma unroll
        for (int ni = 0; ni < 4; ni++)
#pragma unroll
            for (int k = 0; k < 4; k++) acc[mi][ni][k] = 0.f;

    const uint32_t sbase = smem_u32(smg);
    const int lr = t >> 1;
    const int lh = (t & 1) * 16;
    const half* pA = A + (size_t)(row0 + lr) * EE + lh;
    const half* pB = B + (size_t)(col0 + lr) * EE + lh;
    const uint32_t drow = (uint32_t)(lr * GSTR + lh) * 2;

    auto load_stage = [&](int c, int s) {
        const uint32_t sb = sbase + (uint32_t)(s * 2 * GS) * 2 + drow;
        const int ko = c * 32;
        cpa16(sb,          pA + ko);  cpa16(sb + 16,          pA + ko + 8);
        cpa16(sb + GS*2,   pB + ko);  cpa16(sb + GS*2 + 16,   pB + ko + 8);
    };

    load_stage(0, 0);
    CP_COMMIT();

    const int a_row  = lane & 15;
    const int a_half = (lane >> 4) << 3;

    for (int c = 0; c < 32; c++) {
        if (c + 1 < 32) { load_stage(c + 1, (c + 1) & 1); CP_COMMIT(); }
        if (c + 1 < 32) { CP_WAIT1(); } else { CP_WAIT0(); }
        __syncthreads();

        const uint32_t uA = sbase + (uint32_t)((c & 1) * 2 * GS) * 2;
        const uint32_t uB = uA + GS * 2;

#pragma unroll
        for (int ks = 0; ks < 2; ks++) {
            const int kk = ks * 16;
            uint32_t bH[4][2];
#pragma unroll
            for (int u = 0; u < 2; u++) {
                const uint32_t bo = (uint32_t)((wn + u*16 + a_row) * GSTR + kk + a_half) * 2;
                uint32_t r0, r1, r2, r3;
                ldsm_x4(r0, r1, r2, r3, uB + bo);
                bH[2*u][0] = r0; bH[2*u][1] = r2; bH[2*u+1][0] = r1; bH[2*u+1][1] = r3;
            }
#pragma unroll
            for (int mi = 0; mi < 4; mi++) {
                const uint32_t ao = (uint32_t)((wm + mi*16 + a_row) * GSTR + kk + a_half) * 2;
                uint32_t aH[4];
                ldsm_x4(aH[0], aH[1], aH[2], aH[3], uA + ao);
#pragma unroll
                for (int ni = 0; ni < 4; ni++)
                    mma_f16(acc[mi][ni], aH, bH[ni][0], bH[ni][1]);
            }
        }
        __syncthreads();
    }

    // ---- epilogue ----
    const int gr = lane >> 2;
    const int gc = (lane & 3) * 2;
    const float qs = (sel == 0) ? (0.125f * LOG2E) : 1.f;
#pragma unroll
    for (int mi = 0; mi < 4; mi++) {
#pragma unroll
        for (int ni = 0; ni < 4; ni++) {
#pragma unroll
            for (int half_ = 0; half_ < 2; half_++) {
                const int m = row0 + wm + mi*16 + gr + half_*8;
                const int n = col0 + wn + ni*8 + gc;
                float v0 = acc[mi][ni][half_*2+0] + bias[n];
                float v1 = acc[mi][ni][half_*2+1] + bias[n+1];
                if (sel < 0) {
                    *(float2*)&Cout[(size_t)m * EE + n] = make_float2(v0, v1);
                } else {
                    const int b = m >> 11, s = m & 2047;
                    const int hh = n >> 6, d = n & 63;
                    const size_t idx = ((((size_t)b*HH + hh)*SS + s)*DD + d) >> 1;
                    half* outp = (sel == 0) ? g_Q : (sel == 1) ? g_K : g_V;
                    ((uint32_t*)outp)[idx] = pack_h2(v0 * qs, v1 * qs);
                }
            }
        }
    }
}

// ---------------------------------------------------------------------------
// Tensor-core flash attention (pure fp16 MMAs, base-2 online softmax).
// grid (S/128, B*H), 256 threads (8 warps x 16 query rows), 2 CTAs/SM.
// Q fp16 in smem; K/V fp16 double-buffered. Writes fp16 att to g_att [M,E].
// ---------------------------------------------------------------------------
__global__ __launch_bounds__(256, 2) void attn_mma()
{
    extern __shared__ half sma[];
    const int t    = threadIdx.x;
    const int warp = t >> 5;
    const int lane = t & 31;
    const int bh   = blockIdx.y;
    const int q0   = blockIdx.x * 128;
    const int b    = bh >> 4;
    const int h    = bh & 15;

    const uint32_t sbase = smem_u32(sma);
    const uint32_t uQ = sbase;
    const size_t bhoff = (size_t)bh * SS * DD;

    // ---- Q tile -> smem via cp.async (2 threads/row, 32 halves each) ----
    {
        const int qrow = t >> 1;
        const int qch  = (t & 1) * 32;
        const size_t src = bhoff + (size_t)(q0 + qrow)*DD + qch;
        const uint32_t dst = sbase + (uint32_t)(qrow * KSTR + qch) * 2;
#pragma unroll
        for (int c = 0; c < 32; c += 8)
            cpa16(dst + c*2, g_Q + src + c);
    }

    // ---- K/V tile cp.async loaders (full-row coverage, 2 arrays) ----
    const int lrow = t >> 2;
    const int lchk = (t & 3) * 16;
    const uint32_t ddst = (uint32_t)(lrow * KSTR + lchk) * 2;
    auto load_kv = [&](int kb, int s) {
        const size_t src = bhoff + (size_t)(kb*64 + lrow)*DD + lchk;
        const uint32_t sb = sbase + (uint32_t)(QTILE + s * 2 * ATILE) * 2 + ddst;
        cpa16(sb,                 g_K + src);
        cpa16(sb + 16,            g_K + src + 8);
        cpa16(sb + ATILE*2,       g_V + src);
        cpa16(sb + ATILE*2 + 16,  g_V + src + 8);
    };

    float m0 = -1e30f, m1 = -1e30f, l0 = 0.f, l1 = 0.f;
    float oc[8][4];
#pragma unroll
    for (int ni = 0; ni < 8; ni++)
#pragma unroll
        for (int k = 0; k < 4; k++) oc[ni][k] = 0.f;

    load_kv(0, 0);
    CP_COMMIT();

    const int a_row  = lane & 15;
    const int a_half = (lane >> 4) << 3;
    const int g      = lane >> 3;
    const int t_row  = (g & 1)*8 + (lane & 7);
    const int t_col  = (g >> 1)*8;

    for (int kb = 0; kb < SS/64; kb++) {
        if (kb + 1 < SS/64) { load_kv(kb + 1, (kb + 1) & 1); CP_COMMIT(); }
        if (kb + 1 < SS/64) { CP_WAIT1(); } else { CP_WAIT0(); }
        __syncthreads();

        const uint32_t uK = sbase + (uint32_t)(QTILE + (kb & 1) * 2 * ATILE) * 2;
        const uint32_t uV = uK + ATILE*2;

        // ---- S = Q K^T (log2 domain) ----
        float sc[8][4];
#pragma unroll
        for (int ni = 0; ni < 8; ni++)
#pragma unroll
            for (int k = 0; k < 4; k++) sc[ni][k] = 0.f;

#pragma unroll
        for (int ks = 0; ks < 4; ks++) {
            const int kk = ks * 16;
            const uint32_t qo = (uint32_t)((warp*16 + a_row) * KSTR + kk + a_half) * 2;
            uint32_t qh[4];
            ldsm_x4(qh[0], qh[1], qh[2], qh[3], uQ + qo);
#pragma unroll
            for (int u = 0; u < 4; u++) {
                const uint32_t bo = (uint32_t)((u*16 + a_row) * KSTR + kk + a_half) * 2;
                uint32_t r0, r1, r2, r3;
                ldsm_x4(r0, r1, r2, r3, uK + bo);
                mma_f16(sc[2*u],   qh, r0, r2);
                mma_f16(sc[2*u+1], qh, r1, r3);
            }
        }

        // ---- base-2 online softmax ----
        float mx0 = -1e30f, mx1 = -1e30f;
#pragma unroll
        for (int ni = 0; ni < 8; ni++) {
            mx0 = fmaxf(mx0, fmaxf(sc[ni][0], sc[ni][1]));
            mx1 = fmaxf(mx1, fmaxf(sc[ni][2], sc[ni][3]));
        }
        mx0 = fmaxf(mx0, __shfl_xor_sync(0xffffffffu, mx0, 1));
        mx0 = fmaxf(mx0, __shfl_xor_sync(0xffffffffu, mx0, 2));
        mx1 = fmaxf(mx1, __shfl_xor_sync(0xffffffffu, mx1, 1));
        mx1 = fmaxf(mx1, __shfl_xor_sync(0xffffffffu, mx1, 2));
        const float mn0 = fmaxf(m0, mx0), mn1 = fmaxf(m1, mx1);
        const float al0 = ex2(m0 - mn0), al1 = ex2(m1 - mn1);
        float s0 = 0.f, s1 = 0.f;
#pragma unroll
        for (int ni = 0; ni < 8; ni++) {
            sc[ni][0] = ex2(sc[ni][0] - mn0); s0 += sc[ni][0];
            sc[ni][1] = ex2(sc[ni][1] - mn0); s0 += sc[ni][1];
            sc[ni][2] = ex2(sc[ni][2] - mn1); s1 += sc[ni][2];
            sc[ni][3] = ex2(sc[ni][3] - mn1); s1 += sc[ni][3];
        }
        s0 += __shfl_xor_sync(0xffffffffu, s0, 1);
        s0 += __shfl_xor_sync(0xffffffffu, s0, 2);
        s1 += __shfl_xor_sync(0xffffffffu, s1, 1);
        s1 += __shfl_xor_sync(0xffffffffu, s1, 2);
        l0 = l0 * al0 + s0;  l1 = l1 * al1 + s1;
        m0 = mn0;            m1 = mn1;
#pragma unroll
        for (int ni = 0; ni < 8; ni++) {
            oc[ni][0] *= al0; oc[ni][1] *= al0;
            oc[ni][2] *= al1; oc[ni][3] *= al1;
        }

        // ---- O += P V, P packed fp16 ----
#pragma unroll
        for (int ks = 0; ks < 4; ks++) {
            uint32_t ph[4];
            ph[0] = pack_h2(sc[2*ks][0],   sc[2*ks][1]);
            ph[1] = pack_h2(sc[2*ks][2],   sc[2*ks][3]);
            ph[2] = pack_h2(sc[2*ks+1][0], sc[2*ks+1][1]);
            ph[3] = pack_h2(sc[2*ks+1][2], sc[2*ks+1][3]);
            const int keyr = ks*16 + t_row;
#pragma unroll
            for (int p = 0; p < 4; p++) {
                const uint32_t vo = (uint32_t)(keyr * KSTR + 16*p + t_col) * 2;
                uint32_t v0, v1, v2, v3;
                ldsm_x4t(v0, v1, v2, v3, uV + vo);
                mma_f16(oc[2*p],   ph, v0, v1);
                mma_f16(oc[2*p+1], ph, v2, v3);
            }
        }
        __syncthreads();
    }

    // ---- epilogue: normalize, pack fp16, write g_att [M,E] ----
    const float inv0 = 1.f / l0, inv1 = 1.f / l1;
    const int r0row = q0 + warp*16 + (lane >> 2);
#pragma unroll
    for (int ni = 0; ni < 8; ni++) {
        const int d = ni*8 + (lane & 3)*2;
        const size_t col = (size_t)h*DD + d;
        size_t idx = (((size_t)b*SS + r0row)*EE + col) >> 1;
        ((uint32_t*)g_att)[idx] = pack_h2(oc[ni][0]*inv0, oc[ni][1]*inv0);
        idx = (((size_t)b*SS + r0row + 8)*EE + col) >> 1;
        ((uint32_t*)g_att)[idx] = pack_h2(oc[ni][2]*inv1, oc[ni][3]*inv1);
    }
}

// ---------------------------------------------------------------------------
extern "C" void kernel_launch(void* const* d_in, const int* in_sizes, int n_in,
                              void* d_out, int out_size)
{
    const float* x  = (const float*)d_in[0];
    const float* Wq = (const float*)d_in[1];
    const float* bq = (const float*)d_in[2];
    const float* Wk = (const float*)d_in[3];
    const float* bk = (const float*)d_in[4];
    const float* Wv = (const float*)d_in[5];
    const float* bv = (const float*)d_in[6];
    const float* Wo = (const float*)d_in[7];
    const float* bo = (const float*)d_in[8];
    float* out = (float*)d_out;

    half *xp, *ap, *wq, *wk, *wv, *wo;
    cudaGetSymbolAddress((void**)&xp, g_x);   cudaGetSymbolAddress((void**)&ap, g_att);
    cudaGetSymbolAddress((void**)&wq, g_wq);  cudaGetSymbolAddress((void**)&wk, g_wk);
    cudaGetSymbolAddress((void**)&wv, g_wv);  cudaGetSymbolAddress((void**)&wo, g_wo);

    conv_h<<<(MM*EE/4 + 255)/256, 256>>>(x,  xp, MM*EE/4);
    conv_h<<<(EE*EE/4 + 255)/256, 256>>>(Wq, wq, EE*EE/4);
    conv_h<<<(EE*EE/4 + 255)/256, 256>>>(Wk, wk, EE*EE/4);
    conv_h<<<(EE*EE/4 + 255)/256, 256>>>(Wv, wv, EE*EE/4);
    conv_h<<<(EE*EE/4 + 255)/256, 256>>>(Wo, wo, EE*EE/4);

    const int gsmem = 2 * 2 * GS * 2;                 // 40,960 B
    const int asmem = (QTILE + 2 * 2 * ATILE) * 2;    // 55,296 B
    cudaFuncSetAttribute(gemm_1t,  cudaFuncAttributeMaxDynamicSharedMemorySize, gsmem);
    cudaFuncSetAttribute(attn_mma, cudaFuncAttributeMaxDynamicSharedMemorySize, asmem);

    dim3 gp(MM/128, EE/128);
    gemm_1t<<<gp, 256, gsmem>>>(xp, wq, bq, nullptr, 0);
    gemm_1t<<<gp, 256, gsmem>>>(xp, wk, bk, nullptr, 1);
    gemm_1t<<<gp, 256, gsmem>>>(xp, wv, bv, nullptr, 2);

    attn_mma<<<dim3(SS/128, BB*HH), 256, asmem>>>();

    gemm_1t<<<gp, 256, gsmem>>>(ap, wo, bo, out, -1);
}

// round 14
// speedup vs baseline: 9.2641x; 1.0019x over previous
#include <cuda_runtime.h>
#include <cuda_fp16.h>
#include <cstdint>

#define BB 2
#define SS 2048
#define EE 1024
#define HH 16
#define DD 64
#define MM (BB*SS)
#define GSTR 40            // gemm smem row stride (halves)
#define GS (128*GSTR)      // halves per gemm tile array
#define KSTR 72            // attn smem row stride (halves)
#define ATILE (64*KSTR)    // halves per 64-row attn sub-tile
#define QTILE (128*KSTR)   // halves per attn Q tile array
#define LOG2E 1.4426950408889634f

// ---------------- scratch (device globals: allocation-free rule) ------------
__device__ half g_x[MM*EE];                 // x, fp16
__device__ half g_att[MM*EE];               // attention out, fp16
__device__ half g_wq[EE*EE], g_wk[EE*EE], g_wv[EE*EE], g_wo[EE*EE];
__device__ half g_Q[BB*HH*SS*DD];           // pre-scaled by log2e/8
__device__ half g_K[BB*HH*SS*DD];
__device__ half g_V[BB*HH*SS*DD];

// ---------------- helpers ---------------------------------------------------
__device__ __forceinline__ uint32_t smem_u32(const void* p) {
    uint32_t a;
    asm("{ .reg .u64 t; cvta.to.shared.u64 t, %1; cvt.u32.u64 %0, t; }" : "=r"(a) : "l"(p));
    return a;
}
__device__ __forceinline__ void ldsm_x4(uint32_t& r0, uint32_t& r1, uint32_t& r2,
                                        uint32_t& r3, uint32_t addr) {
    asm volatile("ldmatrix.sync.aligned.m8n8.x4.shared.b16 {%0,%1,%2,%3}, [%4];"
                 : "=r"(r0), "=r"(r1), "=r"(r2), "=r"(r3) : "r"(addr));
}
__device__ __forceinline__ void ldsm_x4t(uint32_t& r0, uint32_t& r1, uint32_t& r2,
                                         uint32_t& r3, uint32_t addr) {
    asm volatile("ldmatrix.sync.aligned.m8n8.x4.trans.shared.b16 {%0,%1,%2,%3}, [%4];"
                 : "=r"(r0), "=r"(r1), "=r"(r2), "=r"(r3) : "r"(addr));
}
__device__ __forceinline__ void mma_f16(float* c, const uint32_t* a,
                                        uint32_t b0, uint32_t b1) {
    asm volatile(
        "mma.sync.aligned.m16n8k16.row.col.f32.f16.f16.f32 "
        "{%0,%1,%2,%3}, {%4,%5,%6,%7}, {%8,%9}, {%0,%1,%2,%3};"
        : "+f"(c[0]), "+f"(c[1]), "+f"(c[2]), "+f"(c[3])
        : "r"(a[0]), "r"(a[1]), "r"(a[2]), "r"(a[3]), "r"(b0), "r"(b1));
}
__device__ __forceinline__ void cpa16(uint32_t dst, const void* src) {
    asm volatile("cp.async.cg.shared.global [%0], [%1], 16;" :: "r"(dst), "l"(src));
}
#define CP_COMMIT() asm volatile("cp.async.commit_group;" ::: "memory")
#define CP_WAIT1()  asm volatile("cp.async.wait_group 1;" ::: "memory")
#define CP_WAIT0()  asm volatile("cp.async.wait_group 0;" ::: "memory")

__device__ __forceinline__ float ex2(float x) {
    float r;
    asm("ex2.approx.f32 %0, %1;" : "=f"(r) : "f"(x));
    return r;
}
__device__ __forceinline__ uint32_t pack_h2(float a, float b) {
    __half2 h = __floats2half2_rn(a, b);
    return *(uint32_t*)&h;
}

// ---------------- fused fp32 -> fp16 conversion (x + 4 weights) -------------
// Flat float4 index space: [0, 2^20) -> x; then 4 chunks of 2^18 -> weights.
__global__ __launch_bounds__(256) void conv_fused(
    const float* __restrict__ x,  const float* __restrict__ Wq,
    const float* __restrict__ Wk, const float* __restrict__ Wv,
    const float* __restrict__ Wo)
{
    const int i = blockIdx.x * blockDim.x + threadIdx.x;
    const float* src; half* dst; int off;
    if (i < (1 << 20)) {
        src = x; dst = g_x; off = i;
    } else {
        const int j = i - (1 << 20);
        const int w = j >> 18;
        off = j & ((1 << 18) - 1);
        src = (w == 0) ? Wq : (w == 1) ? Wk : (w == 2) ? Wv : Wo;
        dst = (w == 0) ? g_wq : (w == 1) ? g_wk : (w == 2) ? g_wv : g_wo;
    }
    float4 v = ((const float4*)src)[off];
    ((uint2*)dst)[off] = make_uint2(pack_h2(v.x, v.y), pack_h2(v.z, v.w));
}

// ---------------------------------------------------------------------------
// 1-term fp16 GEMM core (device): C[m,n] ~= sum_k A[m,k]*B[n,k] + bias[n]
// 128x128 CTA tile, BK=32, cp.async double buffer, 8 warps (64x32 tiles).
// ---------------------------------------------------------------------------
__device__ __forceinline__ void gemm_body(
    const half* __restrict__ A, const half* __restrict__ B,
    const float* __restrict__ bias, float* __restrict__ Cout, int sel,
    half* smg, int row0, int col0)
{
    const int t    = threadIdx.x;
    const int warp = t >> 5;
    const int lane = t & 31;
    const int wm   = (warp >> 2) * 64;
    const int wn   = (warp & 3) * 32;

    float acc[4][4][4];
#pragma unroll
    for (int mi = 0; mi < 4; mi++)
#pragma unroll
        for (int ni = 0; ni < 4; ni++)
#pragma unroll
            for (int k = 0; k < 4; k++) acc[mi][ni][k] = 0.f;

    const uint32_t sbase = smem_u32(smg);
    const int lr = t >> 1;
    const int lh = (t & 1) * 16;
    const half* pA = A + (size_t)(row0 + lr) * EE + lh;
    const half* pB = B + (size_t)(col0 + lr) * EE + lh;
    const uint32_t drow = (uint32_t)(lr * GSTR + lh) * 2;

    auto load_stage = [&](int c, int s) {
        const uint32_t sb = sbase + (uint32_t)(s * 2 * GS) * 2 + drow;
        const int ko = c * 32;
        cpa16(sb,          pA + ko);  cpa16(sb + 16,          pA + ko + 8);
        cpa16(sb + GS*2,   pB + ko);  cpa16(sb + GS*2 + 16,   pB + ko + 8);
    };

    load_stage(0, 0);
    CP_COMMIT();

    const int a_row  = lane & 15;
    const int a_half = (lane >> 4) << 3;

    for (int c = 0; c < 32; c++) {
        if (c + 1 < 32) { load_stage(c + 1, (c + 1) & 1); CP_COMMIT(); }
        if (c + 1 < 32) { CP_WAIT1(); } else { CP_WAIT0(); }
        __syncthreads();

        const uint32_t uA = sbase + (uint32_t)((c & 1) * 2 * GS) * 2;
        const uint32_t uB = uA + GS * 2;

#pragma unroll
        for (int ks = 0; ks < 2; ks++) {
            const int kk = ks * 16;
            uint32_t bH[4][2];
#pragma unroll
            for (int u = 0; u < 2; u++) {
                const uint32_t bo = (uint32_t)((wn + u*16 + a_row) * GSTR + kk + a_half) * 2;
                uint32_t r0, r1, r2, r3;
                ldsm_x4(r0, r1, r2, r3, uB + bo);
                bH[2*u][0] = r0; bH[2*u][1] = r2; bH[2*u+1][0] = r1; bH[2*u+1][1] = r3;
            }
#pragma unroll
            for (int mi = 0; mi < 4; mi++) {
                const uint32_t ao = (uint32_t)((wm + mi*16 + a_row) * GSTR + kk + a_half) * 2;
                uint32_t aH[4];
                ldsm_x4(aH[0], aH[1], aH[2], aH[3], uA + ao);
#pragma unroll
                for (int ni = 0; ni < 4; ni++)
                    mma_f16(acc[mi][ni], aH, bH[ni][0], bH[ni][1]);
            }
        }
        __syncthreads();
    }

    // ---- epilogue ----
    const int gr = lane >> 2;
    const int gc = (lane & 3) * 2;
    const float qs = (sel == 0) ? (0.125f * LOG2E) : 1.f;
#pragma unroll
    for (int mi = 0; mi < 4; mi++) {
#pragma unroll
        for (int ni = 0; ni < 4; ni++) {
#pragma unroll
            for (int half_ = 0; half_ < 2; half_++) {
                const int m = row0 + wm + mi*16 + gr + half_*8;
                const int n = col0 + wn + ni*8 + gc;
                float v0 = acc[mi][ni][half_*2+0] + bias[n];
                float v1 = acc[mi][ni][half_*2+1] + bias[n+1];
                if (sel < 0) {
                    *(float2*)&Cout[(size_t)m * EE + n] = make_float2(v0, v1);
                } else {
                    const int b = m >> 11, s = m & 2047;
                    const int hh = n >> 6, d = n & 63;
                    const size_t idx = ((((size_t)b*HH + hh)*SS + s)*DD + d) >> 1;
                    half* outp = (sel == 0) ? g_Q : (sel == 1) ? g_K : g_V;
                    ((uint32_t*)outp)[idx] = pack_h2(v0 * qs, v1 * qs);
                }
            }
        }
    }
}

// Fused QKV projection: gridDim.z = 3 selects weight/bias/output.
__global__ __launch_bounds__(256, 2) void gemm_qkv(
    const float* __restrict__ bq, const float* __restrict__ bk,
    const float* __restrict__ bv)
{
    extern __shared__ half smg[];
    const int z = blockIdx.z;
    const half*  B    = (z == 0) ? g_wq : (z == 1) ? g_wk : g_wv;
    const float* bias = (z == 0) ? bq   : (z == 1) ? bk   : bv;
    gemm_body(g_x, B, bias, nullptr, z, smg, blockIdx.x * 128, blockIdx.y * 128);
}

// Output projection: att @ Wo^T + bo -> f32 out.
__global__ __launch_bounds__(256, 2) void gemm_out(
    const float* __restrict__ bo, float* __restrict__ Cout)
{
    extern __shared__ half smg[];
    gemm_body(g_att, g_wo, bo, Cout, -1, smg, blockIdx.x * 128, blockIdx.y * 128);
}

// ---------------------------------------------------------------------------
// Tensor-core flash attention (pure fp16 MMAs, base-2 online softmax).
// grid (S/128, B*H), 256 threads (8 warps x 16 query rows), 2 CTAs/SM.
// 128-key cp.async stages, two 64-key softmax passes per stage.
// ---------------------------------------------------------------------------
__global__ __launch_bounds__(256, 2) void attn_mma()
{
    extern __shared__ half sma[];
    const int t    = threadIdx.x;
    const int warp = t >> 5;
    const int lane = t & 31;
    const int bh   = blockIdx.y;
    const int q0   = blockIdx.x * 128;
    const int b    = bh >> 4;
    const int h    = bh & 15;

    const uint32_t sbase = smem_u32(sma);
    const uint32_t uQ = sbase;
    const size_t bhoff = (size_t)bh * SS * DD;

    // ---- Q tile -> smem via cp.async (2 threads/row, 32 halves each) ----
    {
        const int qrow = t >> 1;
        const int qch  = (t & 1) * 32;
        const size_t src = bhoff + (size_t)(q0 + qrow)*DD + qch;
        const uint32_t dst = sbase + (uint32_t)(qrow * KSTR + qch) * 2;
#pragma unroll
        for (int c = 0; c < 32; c += 8)
            cpa16(dst + c*2, g_Q + src + c);
    }

    // ---- K/V 128-key stage loaders (2 threads/row, 32 halves each) ----
    // Stage layout: [K rows 0..127 | V rows 0..127], stride KSTR.
    const int lrow = t >> 1;            // 0..127
    const int lchk = (t & 1) * 32;      // halves: 0 or 32
    const uint32_t ddst = (uint32_t)(lrow * KSTR + lchk) * 2;
    auto load_kv = [&](int kb, int s) {
        const size_t src = bhoff + (size_t)(kb*128 + lrow)*DD + lchk;
        const uint32_t sb = sbase + (uint32_t)(QTILE + s * 4 * ATILE) * 2 + ddst;
#pragma unroll
        for (int c = 0; c < 32; c += 8) {
            cpa16(sb + c*2,               g_K + src + c);
            cpa16(sb + 2*ATILE*2 + c*2,   g_V + src + c);
        }
    };

    float m0 = -1e30f, m1 = -1e30f, l0 = 0.f, l1 = 0.f;
    float oc[8][4];
#pragma unroll
    for (int ni = 0; ni < 8; ni++)
#pragma unroll
        for (int k = 0; k < 4; k++) oc[ni][k] = 0.f;

    load_kv(0, 0);
    CP_COMMIT();

    const int a_row  = lane & 15;
    const int a_half = (lane >> 4) << 3;
    const int g      = lane >> 3;
    const int t_row  = (g & 1)*8 + (lane & 7);
    const int t_col  = (g >> 1)*8;

    for (int kb = 0; kb < SS/128; kb++) {
        if (kb + 1 < SS/128) { load_kv(kb + 1, (kb + 1) & 1); CP_COMMIT(); }
        if (kb + 1 < SS/128) { CP_WAIT1(); } else { CP_WAIT0(); }
        __syncthreads();

        const uint32_t uK0 = sbase + (uint32_t)(QTILE + (kb & 1) * 4 * ATILE) * 2;
        const uint32_t uV0 = uK0 + 2*ATILE*2;

#pragma unroll
        for (int p = 0; p < 2; p++) {
            const uint32_t uK = uK0 + p * ATILE * 2;   // key rows p*64..
            const uint32_t uV = uV0 + p * ATILE * 2;

            // ---- S = Q K^T (log2 domain) ----
            float sc[8][4];
#pragma unroll
            for (int ni = 0; ni < 8; ni++)
#pragma unroll
                for (int k = 0; k < 4; k++) sc[ni][k] = 0.f;

#pragma unroll
            for (int ks = 0; ks < 4; ks++) {
                const int kk = ks * 16;
                const uint32_t qo = (uint32_t)((warp*16 + a_row) * KSTR + kk + a_half) * 2;
                uint32_t qh[4];
                ldsm_x4(qh[0], qh[1], qh[2], qh[3], uQ + qo);
#pragma unroll
                for (int u = 0; u < 4; u++) {
                    const uint32_t bo = (uint32_t)((u*16 + a_row) * KSTR + kk + a_half) * 2;
                    uint32_t r0, r1, r2, r3;
                    ldsm_x4(r0, r1, r2, r3, uK + bo);
                    mma_f16(sc[2*u],   qh, r0, r2);
                    mma_f16(sc[2*u+1], qh, r1, r3);
                }
            }

            // ---- base-2 online softmax ----
            float mx0 = -1e30f, mx1 = -1e30f;
#pragma unroll
            for (int ni = 0; ni < 8; ni++) {
                mx0 = fmaxf(mx0, fmaxf(sc[ni][0], sc[ni][1]));
                mx1 = fmaxf(mx1, fmaxf(sc[ni][2], sc[ni][3]));
            }
            mx0 = fmaxf(mx0, __shfl_xor_sync(0xffffffffu, mx0, 1));
            mx0 = fmaxf(mx0, __shfl_xor_sync(0xffffffffu, mx0, 2));
            mx1 = fmaxf(mx1, __shfl_xor_sync(0xffffffffu, mx1, 1));
            mx1 = fmaxf(mx1, __shfl_xor_sync(0xffffffffu, mx1, 2));
            const float mn0 = fmaxf(m0, mx0), mn1 = fmaxf(m1, mx1);
            const float al0 = ex2(m0 - mn0), al1 = ex2(m1 - mn1);
            float s0 = 0.f, s1 = 0.f;
#pragma unroll
            for (int ni = 0; ni < 8; ni++) {
                sc[ni][0] = ex2(sc[ni][0] - mn0); s0 += sc[ni][0];
                sc[ni][1] = ex2(sc[ni][1] - mn0); s0 += sc[ni][1];
                sc[ni][2] = ex2(sc[ni][2] - mn1); s1 += sc[ni][2];
                sc[ni][3] = ex2(sc[ni][3] - mn1); s1 += sc[ni][3];
            }
            s0 += __shfl_xor_sync(0xffffffffu, s0, 1);
            s0 += __shfl_xor_sync(0xffffffffu, s0, 2);
            s1 += __shfl_xor_sync(0xffffffffu, s1, 1);
            s1 += __shfl_xor_sync(0xffffffffu, s1, 2);
            l0 = l0 * al0 + s0;  l1 = l1 * al1 + s1;
            m0 = mn0;            m1 = mn1;
#pragma unroll
            for (int ni = 0; ni < 8; ni++) {
                oc[ni][0] *= al0; oc[ni][1] *= al0;
                oc[ni][2] *= al1; oc[ni][3] *= al1;
            }

            // ---- O += P V, P packed fp16 ----
#pragma unroll
            for (int ks = 0; ks < 4; ks++) {
                uint32_t ph[4];
                ph[0] = pack_h2(sc[2*ks][0],   sc[2*ks][1]);
                ph[1] = pack_h2(sc[2*ks][2],   sc[2*ks][3]);
                ph[2] = pack_h2(sc[2*ks+1][0], sc[2*ks+1][1]);
                ph[3] = pack_h2(sc[2*ks+1][2], sc[2*ks+1][3]);
                const int keyr = ks*16 + t_row;
#pragma unroll
                for (int pp = 0; pp < 4; pp++) {
                    const uint32_t vo = (uint32_t)(keyr * KSTR + 16*pp + t_col) * 2;
                    uint32_t v0, v1, v2, v3;
                    ldsm_x4t(v0, v1, v2, v3, uV + vo);
                    mma_f16(oc[2*pp],   ph, v0, v1);
                    mma_f16(oc[2*pp+1], ph, v2, v3);
                }
            }
        }
        __syncthreads();
    }

    // ---- epilogue: normalize, pack fp16, write g_att [M,E] ----
    const float inv0 = 1.f / l0, inv1 = 1.f / l1;
    const int r0row = q0 + warp*16 + (lane >> 2);
#pragma unroll
    for (int ni = 0; ni < 8; ni++) {
        const int d = ni*8 + (lane & 3)*2;
        const size_t col = (size_t)h*DD + d;
        size_t idx = (((size_t)b*SS + r0row)*EE + col) >> 1;
        ((uint32_t*)g_att)[idx] = pack_h2(oc[ni][0]*inv0, oc[ni][1]*inv0);
        idx = (((size_t)b*SS + r0row + 8)*EE + col) >> 1;
        ((uint32_t*)g_att)[idx] = pack_h2(oc[ni][2]*inv1, oc[ni][3]*inv1);
    }
}

// ---------------------------------------------------------------------------
extern "C" void kernel_launch(void* const* d_in, const int* in_sizes, int n_in,
                              void* d_out, int out_size)
{
    const float* x  = (const float*)d_in[0];
    const float* Wq = (const float*)d_in[1];
    const float* bq = (const float*)d_in[2];
    const float* Wk = (const float*)d_in[3];
    const float* bk = (const float*)d_in[4];
    const float* Wv = (const float*)d_in[5];
    const float* bv = (const float*)d_in[6];
    const float* Wo = (const float*)d_in[7];
    const float* bo = (const float*)d_in[8];
    float* out = (float*)d_out;

    // One fused convert launch: x (2^20 float4) + 4 weights (2^18 each) = 2^21.
    conv_fused<<<(1 << 21) / 256, 256>>>(x, Wq, Wk, Wv, Wo);

    const int gsmem = 2 * 2 * GS * 2;                 // 40,960 B
    const int asmem = (QTILE + 2 * 4 * ATILE) * 2;    // 92,160 B
    cudaFuncSetAttribute(gemm_qkv, cudaFuncAttributeMaxDynamicSharedMemorySize, gsmem);
    cudaFuncSetAttribute(gemm_out, cudaFuncAttributeMaxDynamicSharedMemorySize, gsmem);
    cudaFuncSetAttribute(attn_mma, cudaFuncAttributeMaxDynamicSharedMemorySize, asmem);

    gemm_qkv<<<dim3(MM/128, EE/128, 3), 256, gsmem>>>(bq, bk, bv);

    attn_mma<<<dim3(SS/128, BB*HH), 256, asmem>>>();

    gemm_out<<<dim3(MM/128, EE/128), 256, gsmem>>>(bo, out);
}

// round 15
// speedup vs baseline: 9.3516x; 1.0094x over previous
#include <cuda_runtime.h>
#include <cuda_fp16.h>
#include <cstdint>

#define BB 2
#define SS 2048
#define EE 1024
#define HH 16
#define DD 64
#define MM (BB*SS)
#define GSTR 40            // gemm smem row stride (halves)
#define GS (128*GSTR)      // halves per gemm tile array
#define KSTR 72            // attn smem row stride (halves)
#define ATILE (64*KSTR)    // halves per 64-row attn sub-tile
#define QTILE (128*KSTR)   // halves per attn Q tile array
#define LOG2E 1.4426950408889634f

// ---------------- scratch (device globals: allocation-free rule) ------------
__device__ half g_x[MM*EE];                 // x, fp16
__device__ half g_att[MM*EE];               // attention out, fp16
__device__ half g_wq[EE*EE], g_wk[EE*EE], g_wv[EE*EE], g_wo[EE*EE];
__device__ half g_Q[BB*HH*SS*DD];           // pre-scaled by log2e/8
__device__ half g_K[BB*HH*SS*DD];
__device__ half g_V[BB*HH*SS*DD];

// ---------------- helpers ---------------------------------------------------
__device__ __forceinline__ uint32_t smem_u32(const void* p) {
    uint32_t a;
    asm("{ .reg .u64 t; cvta.to.shared.u64 t, %1; cvt.u32.u64 %0, t; }" : "=r"(a) : "l"(p));
    return a;
}
__device__ __forceinline__ void ldsm_x4(uint32_t& r0, uint32_t& r1, uint32_t& r2,
                                        uint32_t& r3, uint32_t addr) {
    asm volatile("ldmatrix.sync.aligned.m8n8.x4.shared.b16 {%0,%1,%2,%3}, [%4];"
                 : "=r"(r0), "=r"(r1), "=r"(r2), "=r"(r3) : "r"(addr));
}
__device__ __forceinline__ void ldsm_x4t(uint32_t& r0, uint32_t& r1, uint32_t& r2,
                                         uint32_t& r3, uint32_t addr) {
    asm volatile("ldmatrix.sync.aligned.m8n8.x4.trans.shared.b16 {%0,%1,%2,%3}, [%4];"
                 : "=r"(r0), "=r"(r1), "=r"(r2), "=r"(r3) : "r"(addr));
}
__device__ __forceinline__ void mma_f16(float* c, const uint32_t* a,
                                        uint32_t b0, uint32_t b1) {
    asm volatile(
        "mma.sync.aligned.m16n8k16.row.col.f32.f16.f16.f32 "
        "{%0,%1,%2,%3}, {%4,%5,%6,%7}, {%8,%9}, {%0,%1,%2,%3};"
        : "+f"(c[0]), "+f"(c[1]), "+f"(c[2]), "+f"(c[3])
        : "r"(a[0]), "r"(a[1]), "r"(a[2]), "r"(a[3]), "r"(b0), "r"(b1));
}
__device__ __forceinline__ void cpa16(uint32_t dst, const void* src) {
    asm volatile("cp.async.cg.shared.global [%0], [%1], 16;" :: "r"(dst), "l"(src));
}
#define CP_COMMIT() asm volatile("cp.async.commit_group;" ::: "memory")
#define CP_WAIT1()  asm volatile("cp.async.wait_group 1;" ::: "memory")
#define CP_WAIT0()  asm volatile("cp.async.wait_group 0;" ::: "memory")

__device__ __forceinline__ float ex2(float x) {
    float r;
    asm("ex2.approx.f32 %0, %1;" : "=f"(r) : "f"(x));
    return r;
}
__device__ __forceinline__ uint32_t pack_h2(float a, float b) {
    __half2 h = __floats2half2_rn(a, b);
    return *(uint32_t*)&h;
}

// ---------------- fused fp32 -> fp16 conversion (x + 4 weights) -------------
__global__ __launch_bounds__(256) void conv_fused(
    const float* __restrict__ x,  const float* __restrict__ Wq,
    const float* __restrict__ Wk, const float* __restrict__ Wv,
    const float* __restrict__ Wo)
{
    const int i = blockIdx.x * blockDim.x + threadIdx.x;
    const float* src; half* dst; int off;
    if (i < (1 << 20)) {
        src = x; dst = g_x; off = i;
    } else {
        const int j = i - (1 << 20);
        const int w = j >> 18;
        off = j & ((1 << 18) - 1);
        src = (w == 0) ? Wq : (w == 1) ? Wk : (w == 2) ? Wv : Wo;
        dst = (w == 0) ? g_wq : (w == 1) ? g_wk : (w == 2) ? g_wv : g_wo;
    }
    float4 v = ((const float4*)src)[off];
    ((uint2*)dst)[off] = make_uint2(pack_h2(v.x, v.y), pack_h2(v.z, v.w));
}

// ---------------------------------------------------------------------------
// 1-term fp16 GEMM core: 128x128 CTA tile, BK=32, 3-stage cp.async pipeline,
// ONE __syncthreads per k-chunk. 8 warps (64x32 warp tiles).
// ---------------------------------------------------------------------------
__device__ __forceinline__ void gemm_body(
    const half* __restrict__ A, const half* __restrict__ B,
    const float* __restrict__ bias, float* __restrict__ Cout, int sel,
    half* smg, int row0, int col0)
{
    const int t    = threadIdx.x;
    const int warp = t >> 5;
    const int lane = t & 31;
    const int wm   = (warp >> 2) * 64;
    const int wn   = (warp & 3) * 32;

    float acc[4][4][4];
#pragma unroll
    for (int mi = 0; mi < 4; mi++)
#pragma unroll
        for (int ni = 0; ni < 4; ni++)
#pragma unroll
            for (int k = 0; k < 4; k++) acc[mi][ni][k] = 0.f;

    const uint32_t sbase = smem_u32(smg);
    const int lr = t >> 1;
    const int lh = (t & 1) * 16;
    const half* pA = A + (size_t)(row0 + lr) * EE + lh;
    const half* pB = B + (size_t)(col0 + lr) * EE + lh;
    const uint32_t drow = (uint32_t)(lr * GSTR + lh) * 2;

    auto load_stage = [&](int c, int s) {
        const uint32_t sb = sbase + (uint32_t)(s * 2 * GS) * 2 + drow;
        const int ko = c * 32;
        cpa16(sb,          pA + ko);  cpa16(sb + 16,          pA + ko + 8);
        cpa16(sb + GS*2,   pB + ko);  cpa16(sb + GS*2 + 16,   pB + ko + 8);
    };

    // prefetch stages 0,1
    load_stage(0, 0); CP_COMMIT();
    load_stage(1, 1); CP_COMMIT();

    const int a_row  = lane & 15;
    const int a_half = (lane >> 4) << 3;

    for (int c = 0; c < 32; c++) {
        if (c < 31) { CP_WAIT1(); } else { CP_WAIT0(); }
        __syncthreads();
        // safe: buffer (c+2)%3 was last read in iter c-1; the sync above
        // guarantees all warps have passed that compute.
        if (c + 2 < 32) { load_stage(c + 2, (c + 2) % 3); CP_COMMIT(); }

        const uint32_t uA = sbase + (uint32_t)((c % 3) * 2 * GS) * 2;
        const uint32_t uB = uA + GS * 2;

#pragma unroll
        for (int ks = 0; ks < 2; ks++) {
            const int kk = ks * 16;
            uint32_t bH[4][2];
#pragma unroll
            for (int u = 0; u < 2; u++) {
                const uint32_t bo = (uint32_t)((wn + u*16 + a_row) * GSTR + kk + a_half) * 2;
                uint32_t r0, r1, r2, r3;
                ldsm_x4(r0, r1, r2, r3, uB + bo);
                bH[2*u][0] = r0; bH[2*u][1] = r2; bH[2*u+1][0] = r1; bH[2*u+1][1] = r3;
            }
#pragma unroll
            for (int mi = 0; mi < 4; mi++) {
                const uint32_t ao = (uint32_t)((wm + mi*16 + a_row) * GSTR + kk + a_half) * 2;
                uint32_t aH[4];
                ldsm_x4(aH[0], aH[1], aH[2], aH[3], uA + ao);
#pragma unroll
                for (int ni = 0; ni < 4; ni++)
                    mma_f16(acc[mi][ni], aH, bH[ni][0], bH[ni][1]);
            }
        }
    }

    // ---- epilogue ----
    const int gr = lane >> 2;
    const int gc = (lane & 3) * 2;
    const float qs = (sel == 0) ? (0.125f * LOG2E) : 1.f;
#pragma unroll
    for (int mi = 0; mi < 4; mi++) {
#pragma unroll
        for (int ni = 0; ni < 4; ni++) {
#pragma unroll
            for (int half_ = 0; half_ < 2; half_++) {
                const int m = row0 + wm + mi*16 + gr + half_*8;
                const int n = col0 + wn + ni*8 + gc;
                float v0 = acc[mi][ni][half_*2+0] + bias[n];
                float v1 = acc[mi][ni][half_*2+1] + bias[n+1];
                if (sel < 0) {
                    *(float2*)&Cout[(size_t)m * EE + n] = make_float2(v0, v1);
                } else {
                    const int b = m >> 11, s = m & 2047;
                    const int hh = n >> 6, d = n & 63;
                    const size_t idx = ((((size_t)b*HH + hh)*SS + s)*DD + d) >> 1;
                    half* outp = (sel == 0) ? g_Q : (sel == 1) ? g_K : g_V;
                    ((uint32_t*)outp)[idx] = pack_h2(v0 * qs, v1 * qs);
                }
            }
        }
    }
}

// Fused QKV projection: gridDim.z = 3 selects weight/bias/output.
__global__ __launch_bounds__(256, 2) void gemm_qkv(
    const float* __restrict__ bq, const float* __restrict__ bk,
    const float* __restrict__ bv)
{
    extern __shared__ half smg[];
    const int z = blockIdx.z;
    const half*  B    = (z == 0) ? g_wq : (z == 1) ? g_wk : g_wv;
    const float* bias = (z == 0) ? bq   : (z == 1) ? bk   : bv;
    gemm_body(g_x, B, bias, nullptr, z, smg, blockIdx.x * 128, blockIdx.y * 128);
}

// Output projection: att @ Wo^T + bo -> f32 out.
__global__ __launch_bounds__(256, 2) void gemm_out(
    const float* __restrict__ bo, float* __restrict__ Cout)
{
    extern __shared__ half smg[];
    gemm_body(g_att, g_wo, bo, Cout, -1, smg, blockIdx.x * 128, blockIdx.y * 128);
}

// ---------------------------------------------------------------------------
// Tensor-core flash attention (pure fp16 MMAs, base-2 online softmax).
// grid (S/128, B*H), 256 threads (8 warps x 16 query rows), 2 CTAs/SM.
// 128-key cp.async stages, ONE __syncthreads per stage.
// ---------------------------------------------------------------------------
__global__ __launch_bounds__(256, 2) void attn_mma()
{
    extern __shared__ half sma[];
    const int t    = threadIdx.x;
    const int warp = t >> 5;
    const int lane = t & 31;
    const int bh   = blockIdx.y;
    const int q0   = blockIdx.x * 128;
    const int b    = bh >> 4;
    const int h    = bh & 15;

    const uint32_t sbase = smem_u32(sma);
    const uint32_t uQ = sbase;
    const size_t bhoff = (size_t)bh * SS * DD;

    // ---- Q tile -> smem via cp.async (2 threads/row, 32 halves each) ----
    {
        const int qrow = t >> 1;
        const int qch  = (t & 1) * 32;
        const size_t src = bhoff + (size_t)(q0 + qrow)*DD + qch;
        const uint32_t dst = sbase + (uint32_t)(qrow * KSTR + qch) * 2;
#pragma unroll
        for (int c = 0; c < 32; c += 8)
            cpa16(dst + c*2, g_Q + src + c);
    }

    // ---- K/V 128-key stage loaders (2 threads/row, 32 halves each) ----
    const int lrow = t >> 1;            // 0..127
    const int lchk = (t & 1) * 32;      // halves: 0 or 32
    const uint32_t ddst = (uint32_t)(lrow * KSTR + lchk) * 2;
    auto load_kv = [&](int kb, int s) {
        const size_t src = bhoff + (size_t)(kb*128 + lrow)*DD + lchk;
        const uint32_t sb = sbase + (uint32_t)(QTILE + s * 4 * ATILE) * 2 + ddst;
#pragma unroll
        for (int c = 0; c < 32; c += 8) {
            cpa16(sb + c*2,               g_K + src + c);
            cpa16(sb + 2*ATILE*2 + c*2,   g_V + src + c);
        }
    };

    float m0 = -1e30f, m1 = -1e30f, l0 = 0.f, l1 = 0.f;
    float oc[8][4];
#pragma unroll
    for (int ni = 0; ni < 8; ni++)
#pragma unroll
        for (int k = 0; k < 4; k++) oc[ni][k] = 0.f;

    load_kv(0, 0);      // Q + stage 0 in one group
    CP_COMMIT();

    const int a_row  = lane & 15;
    const int a_half = (lane >> 4) << 3;
    const int g      = lane >> 3;
    const int t_row  = (g & 1)*8 + (lane & 7);
    const int t_col  = (g >> 1)*8;

    for (int kb = 0; kb < SS/128; kb++) {
        CP_WAIT0();
        __syncthreads();
        // safe: buffer (kb+1)&1 was last read in iter kb-1; sync above
        // guarantees all warps passed that compute. Loads overlap compute kb.
        if (kb + 1 < SS/128) { load_kv(kb + 1, (kb + 1) & 1); CP_COMMIT(); }

        const uint32_t uK0 = sbase + (uint32_t)(QTILE + (kb & 1) * 4 * ATILE) * 2;
        const uint32_t uV0 = uK0 + 2*ATILE*2;

#pragma unroll
        for (int p = 0; p < 2; p++) {
            const uint32_t uK = uK0 + p * ATILE * 2;
            const uint32_t uV = uV0 + p * ATILE * 2;

            // ---- S = Q K^T (log2 domain) ----
            float sc[8][4];
#pragma unroll
            for (int ni = 0; ni < 8; ni++)
#pragma unroll
                for (int k = 0; k < 4; k++) sc[ni][k] = 0.f;

#pragma unroll
            for (int ks = 0; ks < 4; ks++) {
                const int kk = ks * 16;
                const uint32_t qo = (uint32_t)((warp*16 + a_row) * KSTR + kk + a_half) * 2;
                uint32_t qh[4];
                ldsm_x4(qh[0], qh[1], qh[2], qh[3], uQ + qo);
#pragma unroll
                for (int u = 0; u < 4; u++) {
                    const uint32_t bo = (uint32_t)((u*16 + a_row) * KSTR + kk + a_half) * 2;
                    uint32_t r0, r1, r2, r3;
                    ldsm_x4(r0, r1, r2, r3, uK + bo);
                    mma_f16(sc[2*u],   qh, r0, r2);
                    mma_f16(sc[2*u+1], qh, r1, r3);
                }
            }

            // ---- base-2 online softmax ----
            float mx0 = -1e30f, mx1 = -1e30f;
#pragma unroll
            for (int ni = 0; ni < 8; ni++) {
                mx0 = fmaxf(mx0, fmaxf(sc[ni][0], sc[ni][1]));
                mx1 = fmaxf(mx1, fmaxf(sc[ni][2], sc[ni][3]));
            }
            mx0 = fmaxf(mx0, __shfl_xor_sync(0xffffffffu, mx0, 1));
            mx0 = fmaxf(mx0, __shfl_xor_sync(0xffffffffu, mx0, 2));
            mx1 = fmaxf(mx1, __shfl_xor_sync(0xffffffffu, mx1, 1));
            mx1 = fmaxf(mx1, __shfl_xor_sync(0xffffffffu, mx1, 2));
            const float mn0 = fmaxf(m0, mx0), mn1 = fmaxf(m1, mx1);
            const float al0 = ex2(m0 - mn0), al1 = ex2(m1 - mn1);
            float s0 = 0.f, s1 = 0.f;
#pragma unroll
            for (int ni = 0; ni < 8; ni++) {
                sc[ni][0] = ex2(sc[ni][0] - mn0); s0 += sc[ni][0];
                sc[ni][1] = ex2(sc[ni][1] - mn0); s0 += sc[ni][1];
                sc[ni][2] = ex2(sc[ni][2] - mn1); s1 += sc[ni][2];
                sc[ni][3] = ex2(sc[ni][3] - mn1); s1 += sc[ni][3];
            }
            s0 += __shfl_xor_sync(0xffffffffu, s0, 1);
            s0 += __shfl_xor_sync(0xffffffffu, s0, 2);
            s1 += __shfl_xor_sync(0xffffffffu, s1, 1);
            s1 += __shfl_xor_sync(0xffffffffu, s1, 2);
            l0 = l0 * al0 + s0;  l1 = l1 * al1 + s1;
            m0 = mn0;            m1 = mn1;
#pragma unroll
            for (int ni = 0; ni < 8; ni++) {
                oc[ni][0] *= al0; oc[ni][1] *= al0;
                oc[ni][2] *= al1; oc[ni][3] *= al1;
            }

            // ---- O += P V, P packed fp16 ----
#pragma unroll
            for (int ks = 0; ks < 4; ks++) {
                uint32_t ph[4];
                ph[0] = pack_h2(sc[2*ks][0],   sc[2*ks][1]);
                ph[1] = pack_h2(sc[2*ks][2],   sc[2*ks][3]);
                ph[2] = pack_h2(sc[2*ks+1][0], sc[2*ks+1][1]);
                ph[3] = pack_h2(sc[2*ks+1][2], sc[2*ks+1][3]);
                const int keyr = ks*16 + t_row;
#pragma unroll
                for (int pp = 0; pp < 4; pp++) {
                    const uint32_t vo = (uint32_t)(keyr * KSTR + 16*pp + t_col) * 2;
                    uint32_t v0, v1, v2, v3;
                    ldsm_x4t(v0, v1, v2, v3, uV + vo);
                    mma_f16(oc[2*pp],   ph, v0, v1);
                    mma_f16(oc[2*pp+1], ph, v2, v3);
                }
            }
        }
    }

    // ---- epilogue: normalize, pack fp16, write g_att [M,E] ----
    const float inv0 = 1.f / l0, inv1 = 1.f / l1;
    const int r0row = q0 + warp*16 + (lane >> 2);
#pragma unroll
    for (int ni = 0; ni < 8; ni++) {
        const int d = ni*8 + (lane & 3)*2;
        const size_t col = (size_t)h*DD + d;
        size_t idx = (((size_t)b*SS + r0row)*EE + col) >> 1;
        ((uint32_t*)g_att)[idx] = pack_h2(oc[ni][0]*inv0, oc[ni][1]*inv0);
        idx = (((size_t)b*SS + r0row + 8)*EE + col) >> 1;
        ((uint32_t*)g_att)[idx] = pack_h2(oc[ni][2]*inv1, oc[ni][3]*inv1);
    }
}

// ---------------------------------------------------------------------------
extern "C" void kernel_launch(void* const* d_in, const int* in_sizes, int n_in,
                              void* d_out, int out_size)
{
    const float* x  = (const float*)d_in[0];
    const float* Wq = (const float*)d_in[1];
    const float* bq = (const float*)d_in[2];
    const float* Wk = (const float*)d_in[3];
    const float* bk = (const float*)d_in[4];
    const float* Wv = (const float*)d_in[5];
    const float* bv = (const float*)d_in[6];
    const float* Wo = (const float*)d_in[7];
    const float* bo = (const float*)d_in[8];
    float* out = (float*)d_out;

    conv_fused<<<(1 << 21) / 256, 256>>>(x, Wq, Wk, Wv, Wo);

    const int gsmem = 3 * 2 * GS * 2;                 // 61,440 B (3 stages)
    const int asmem = (QTILE + 2 * 4 * ATILE) * 2;    // 92,160 B
    cudaFuncSetAttribute(gemm_qkv, cudaFuncAttributeMaxDynamicSharedMemorySize, gsmem);
    cudaFuncSetAttribute(gemm_out, cudaFuncAttributeMaxDynamicSharedMemorySize, gsmem);
    cudaFuncSetAttribute(attn_mma, cudaFuncAttributeMaxDynamicSharedMemorySize, asmem);

    gemm_qkv<<<dim3(MM/128, EE/128, 3), 256, gsmem>>>(bq, bk, bv);

    attn_mma<<<dim3(SS/128, BB*HH), 256, asmem>>>();

    gemm_out<<<dim3(MM/128, EE/128), 256, gsmem>>>(bo, out);
}

// round 16
// speedup vs baseline: 9.5153x; 1.0175x over previous
#include <cuda_runtime.h>
#include <cuda_fp16.h>
#include <cstdint>

#define BB 2
#define SS 2048
#define EE 1024
#define HH 16
#define DD 64
#define MM (BB*SS)
#define GSTR 40            // gemm smem row stride (halves)
#define GS (128*GSTR)      // halves per gemm tile array
#define KSTR 72            // attn smem row stride (halves)
#define ATILE (64*KSTR)    // halves per 64-row attn sub-tile
#define QTILE (128*KSTR)   // halves per attn Q tile array
#define LOG2E 1.4426950408889634f

// ---------------- scratch (device globals: allocation-free rule) ------------
__device__ half g_x[MM*EE];                 // x, fp16
__device__ half g_att[MM*EE];               // attention out, fp16
__device__ half g_wq[EE*EE], g_wk[EE*EE], g_wv[EE*EE], g_wo[EE*EE];
__device__ half g_Q[BB*HH*SS*DD];           // pre-scaled by log2e/8
__device__ half g_K[BB*HH*SS*DD];
__device__ half g_V[BB*HH*SS*DD];

// ---------------- helpers ---------------------------------------------------
__device__ __forceinline__ uint32_t smem_u32(const void* p) {
    uint32_t a;
    asm("{ .reg .u64 t; cvta.to.shared.u64 t, %1; cvt.u32.u64 %0, t; }" : "=r"(a) : "l"(p));
    return a;
}
__device__ __forceinline__ void ldsm_x4(uint32_t& r0, uint32_t& r1, uint32_t& r2,
                                        uint32_t& r3, uint32_t addr) {
    asm volatile("ldmatrix.sync.aligned.m8n8.x4.shared.b16 {%0,%1,%2,%3}, [%4];"
                 : "=r"(r0), "=r"(r1), "=r"(r2), "=r"(r3) : "r"(addr));
}
__device__ __forceinline__ void ldsm_x4t(uint32_t& r0, uint32_t& r1, uint32_t& r2,
                                         uint32_t& r3, uint32_t addr) {
    asm volatile("ldmatrix.sync.aligned.m8n8.x4.trans.shared.b16 {%0,%1,%2,%3}, [%4];"
                 : "=r"(r0), "=r"(r1), "=r"(r2), "=r"(r3) : "r"(addr));
}
__device__ __forceinline__ void mma_f16(float* c, const uint32_t* a,
                                        uint32_t b0, uint32_t b1) {
    asm volatile(
        "mma.sync.aligned.m16n8k16.row.col.f32.f16.f16.f32 "
        "{%0,%1,%2,%3}, {%4,%5,%6,%7}, {%8,%9}, {%0,%1,%2,%3};"
        : "+f"(c[0]), "+f"(c[1]), "+f"(c[2]), "+f"(c[3])
        : "r"(a[0]), "r"(a[1]), "r"(a[2]), "r"(a[3]), "r"(b0), "r"(b1));
}
__device__ __forceinline__ void cpa16(uint32_t dst, const void* src) {
    asm volatile("cp.async.cg.shared.global [%0], [%1], 16;" :: "r"(dst), "l"(src));
}
#define CP_COMMIT() asm volatile("cp.async.commit_group;" ::: "memory")
#define CP_WAIT1()  asm volatile("cp.async.wait_group 1;" ::: "memory")
#define CP_WAIT0()  asm volatile("cp.async.wait_group 0;" ::: "memory")

__device__ __forceinline__ float ex2(float x) {
    float r;
    asm("ex2.approx.f32 %0, %1;" : "=f"(r) : "f"(x));
    return r;
}
__device__ __forceinline__ uint32_t pack_h2(float a, float b) {
    __half2 h = __floats2half2_rn(a, b);
    return *(uint32_t*)&h;
}

// ---------------- fused fp32 -> fp16 conversion (x + 4 weights) -------------
__global__ __launch_bounds__(256) void conv_fused(
    const float* __restrict__ x,  const float* __restrict__ Wq,
    const float* __restrict__ Wk, const float* __restrict__ Wv,
    const float* __restrict__ Wo)
{
    const int i = blockIdx.x * blockDim.x + threadIdx.x;
    const float* src; half* dst; int off;
    if (i < (1 << 20)) {
        src = x; dst = g_x; off = i;
    } else {
        const int j = i - (1 << 20);
        const int w = j >> 18;
        off = j & ((1 << 18) - 1);
        src = (w == 0) ? Wq : (w == 1) ? Wk : (w == 2) ? Wv : Wo;
        dst = (w == 0) ? g_wq : (w == 1) ? g_wk : (w == 2) ? g_wv : g_wo;
    }
    float4 v = ((const float4*)src)[off];
    ((uint2*)dst)[off] = make_uint2(pack_h2(v.x, v.y), pack_h2(v.z, v.w));
}

// ---------------------------------------------------------------------------
// 1-term fp16 GEMM core: 128x128 CTA tile, BK=32, 3-stage cp.async pipeline.
// Fragment-pipelined inner loop: all B frags hoisted per chunk; A frags per
// mi for both k-steps, MMAs batched after (8 MMA per 2 exposed LDSM).
// ---------------------------------------------------------------------------
__device__ __forceinline__ void gemm_body(
    const half* __restrict__ A, const half* __restrict__ B,
    const float* __restrict__ bias, float* __restrict__ Cout, int sel,
    half* smg, int row0, int col0)
{
    const int t    = threadIdx.x;
    const int warp = t >> 5;
    const int lane = t & 31;
    const int wm   = (warp >> 2) * 64;
    const int wn   = (warp & 3) * 32;

    float acc[4][4][4];
#pragma unroll
    for (int mi = 0; mi < 4; mi++)
#pragma unroll
        for (int ni = 0; ni < 4; ni++)
#pragma unroll
            for (int k = 0; k < 4; k++) acc[mi][ni][k] = 0.f;

    const uint32_t sbase = smem_u32(smg);
    const int lr = t >> 1;
    const int lh = (t & 1) * 16;
    const half* pA = A + (size_t)(row0 + lr) * EE + lh;
    const half* pB = B + (size_t)(col0 + lr) * EE + lh;
    const uint32_t drow = (uint32_t)(lr * GSTR + lh) * 2;

    auto load_stage = [&](int c, int s) {
        const uint32_t sb = sbase + (uint32_t)(s * 2 * GS) * 2 + drow;
        const int ko = c * 32;
        cpa16(sb,          pA + ko);  cpa16(sb + 16,          pA + ko + 8);
        cpa16(sb + GS*2,   pB + ko);  cpa16(sb + GS*2 + 16,   pB + ko + 8);
    };

    load_stage(0, 0); CP_COMMIT();
    load_stage(1, 1); CP_COMMIT();

    const int a_row  = lane & 15;
    const int a_half = (lane >> 4) << 3;

    for (int c = 0; c < 32; c++) {
        if (c < 31) { CP_WAIT1(); } else { CP_WAIT0(); }
        __syncthreads();
        if (c + 2 < 32) { load_stage(c + 2, (c + 2) % 3); CP_COMMIT(); }

        const uint32_t uA = sbase + (uint32_t)((c % 3) * 2 * GS) * 2;
        const uint32_t uB = uA + GS * 2;

        // ---- hoist all B fragments for this chunk: [ks][ni][2] ----
        uint32_t bF[2][4][2];
#pragma unroll
        for (int ks = 0; ks < 2; ks++) {
#pragma unroll
            for (int u = 0; u < 2; u++) {
                const uint32_t bo = (uint32_t)((wn + u*16 + a_row) * GSTR + ks*16 + a_half) * 2;
                uint32_t r0, r1, r2, r3;
                ldsm_x4(r0, r1, r2, r3, uB + bo);
                bF[ks][2*u][0] = r0; bF[ks][2*u][1] = r2;
                bF[ks][2*u+1][0] = r1; bF[ks][2*u+1][1] = r3;
            }
        }
        // ---- per mi: both k-step A frags, then 8 MMAs ----
#pragma unroll
        for (int mi = 0; mi < 4; mi++) {
            uint32_t aF[2][4];
            const uint32_t ao = (uint32_t)((wm + mi*16 + a_row) * GSTR + a_half) * 2;
            ldsm_x4(aF[0][0], aF[0][1], aF[0][2], aF[0][3], uA + ao);
            ldsm_x4(aF[1][0], aF[1][1], aF[1][2], aF[1][3], uA + ao + 16*2);
#pragma unroll
            for (int ks = 0; ks < 2; ks++)
#pragma unroll
                for (int ni = 0; ni < 4; ni++)
                    mma_f16(acc[mi][ni], aF[ks], bF[ks][ni][0], bF[ks][ni][1]);
        }
    }

    // ---- epilogue ----
    const int gr = lane >> 2;
    const int gc = (lane & 3) * 2;
    const float qs = (sel == 0) ? (0.125f * LOG2E) : 1.f;
#pragma unroll
    for (int mi = 0; mi < 4; mi++) {
#pragma unroll
        for (int ni = 0; ni < 4; ni++) {
#pragma unroll
            for (int half_ = 0; half_ < 2; half_++) {
                const int m = row0 + wm + mi*16 + gr + half_*8;
                const int n = col0 + wn + ni*8 + gc;
                float v0 = acc[mi][ni][half_*2+0] + bias[n];
                float v1 = acc[mi][ni][half_*2+1] + bias[n+1];
                if (sel < 0) {
                    *(float2*)&Cout[(size_t)m * EE + n] = make_float2(v0, v1);
                } else {
                    const int b = m >> 11, s = m & 2047;
                    const int hh = n >> 6, d = n & 63;
                    const size_t idx = ((((size_t)b*HH + hh)*SS + s)*DD + d) >> 1;
                    half* outp = (sel == 0) ? g_Q : (sel == 1) ? g_K : g_V;
                    ((uint32_t*)outp)[idx] = pack_h2(v0 * qs, v1 * qs);
                }
            }
        }
    }
}

// Fused QKV projection: gridDim.z = 3 selects weight/bias/output.
__global__ __launch_bounds__(256, 2) void gemm_qkv(
    const float* __restrict__ bq, const float* __restrict__ bk,
    const float* __restrict__ bv)
{
    extern __shared__ half smg[];
    const int z = blockIdx.z;
    const half*  B    = (z == 0) ? g_wq : (z == 1) ? g_wk : g_wv;
    const float* bias = (z == 0) ? bq   : (z == 1) ? bk   : bv;
    gemm_body(g_x, B, bias, nullptr, z, smg, blockIdx.x * 128, blockIdx.y * 128);
}

__global__ __launch_bounds__(256, 2) void gemm_out(
    const float* __restrict__ bo, float* __restrict__ Cout)
{
    extern __shared__ half smg[];
    gemm_body(g_att, g_wo, bo, Cout, -1, smg, blockIdx.x * 128, blockIdx.y * 128);
}

// ---------------------------------------------------------------------------
// Tensor-core flash attention (pure fp16 MMAs, base-2 online softmax).
// grid (S/128, B*H), 256 threads (8 warps x 16 query rows), 2 CTAs/SM.
// Q fragments held in registers across the whole loop (loop-invariant).
// K/V fragments loaded in batches before their MMA groups.
// ---------------------------------------------------------------------------
__global__ __launch_bounds__(256, 2) void attn_mma()
{
    extern __shared__ half sma[];
    const int t    = threadIdx.x;
    const int warp = t >> 5;
    const int lane = t & 31;
    const int bh   = blockIdx.y;
    const int q0   = blockIdx.x * 128;
    const int b    = bh >> 4;
    const int h    = bh & 15;

    const uint32_t sbase = smem_u32(sma);
    const uint32_t uQ = sbase;
    const size_t bhoff = (size_t)bh * SS * DD;

    // ---- Q tile -> smem via cp.async ----
    {
        const int qrow = t >> 1;
        const int qch  = (t & 1) * 32;
        const size_t src = bhoff + (size_t)(q0 + qrow)*DD + qch;
        const uint32_t dst = sbase + (uint32_t)(qrow * KSTR + qch) * 2;
#pragma unroll
        for (int c = 0; c < 32; c += 8)
            cpa16(dst + c*2, g_Q + src + c);
    }

    // ---- K/V 128-key stage loaders ----
    const int lrow = t >> 1;
    const int lchk = (t & 1) * 32;
    const uint32_t ddst = (uint32_t)(lrow * KSTR + lchk) * 2;
    auto load_kv = [&](int kb, int s) {
        const size_t src = bhoff + (size_t)(kb*128 + lrow)*DD + lchk;
        const uint32_t sb = sbase + (uint32_t)(QTILE + s * 4 * ATILE) * 2 + ddst;
#pragma unroll
        for (int c = 0; c < 32; c += 8) {
            cpa16(sb + c*2,               g_K + src + c);
            cpa16(sb + 2*ATILE*2 + c*2,   g_V + src + c);
        }
    };

    float m0 = -1e30f, m1 = -1e30f, l0 = 0.f, l1 = 0.f;
    float oc[8][4];
#pragma unroll
    for (int ni = 0; ni < 8; ni++)
#pragma unroll
        for (int k = 0; k < 4; k++) oc[ni][k] = 0.f;

    load_kv(0, 0);      // Q + stage 0 in one group
    CP_COMMIT();

    const int a_row  = lane & 15;
    const int a_half = (lane >> 4) << 3;
    const int g      = lane >> 3;
    const int t_row  = (g & 1)*8 + (lane & 7);
    const int t_col  = (g >> 1)*8;

    // ---- wait for Q + stage 0, then hoist Q fragments (loop-invariant) ----
    CP_WAIT0();
    __syncthreads();
    uint32_t qF[4][4];
#pragma unroll
    for (int ks = 0; ks < 4; ks++) {
        const uint32_t qo = (uint32_t)((warp*16 + a_row) * KSTR + ks*16 + a_half) * 2;
        ldsm_x4(qF[ks][0], qF[ks][1], qF[ks][2], qF[ks][3], uQ + qo);
    }

    for (int kb = 0; kb < SS/128; kb++) {
        if (kb > 0) { CP_WAIT0(); __syncthreads(); }
        if (kb + 1 < SS/128) { load_kv(kb + 1, (kb + 1) & 1); CP_COMMIT(); }

        const uint32_t uK0 = sbase + (uint32_t)(QTILE + (kb & 1) * 4 * ATILE) * 2;
        const uint32_t uV0 = uK0 + 2*ATILE*2;

#pragma unroll
        for (int p = 0; p < 2; p++) {
            const uint32_t uK = uK0 + p * ATILE * 2;
            const uint32_t uV = uV0 + p * ATILE * 2;

            // ---- S = Q K^T (log2 domain): batch 4 K-ldsm, then 8 MMAs ----
            float sc[8][4];
#pragma unroll
            for (int ni = 0; ni < 8; ni++)
#pragma unroll
                for (int k = 0; k < 4; k++) sc[ni][k] = 0.f;

#pragma unroll
            for (int ks = 0; ks < 4; ks++) {
                uint32_t kF[4][4];
#pragma unroll
                for (int u = 0; u < 4; u++) {
                    const uint32_t bo = (uint32_t)((u*16 + a_row) * KSTR + ks*16 + a_half) * 2;
                    ldsm_x4(kF[u][0], kF[u][1], kF[u][2], kF[u][3], uK + bo);
                }
#pragma unroll
                for (int u = 0; u < 4; u++) {
                    mma_f16(sc[2*u],   qF[ks], kF[u][0], kF[u][2]);
                    mma_f16(sc[2*u+1], qF[ks], kF[u][1], kF[u][3]);
                }
            }

            // ---- base-2 online softmax ----
            float mx0 = -1e30f, mx1 = -1e30f;
#pragma unroll
            for (int ni = 0; ni < 8; ni++) {
                mx0 = fmaxf(mx0, fmaxf(sc[ni][0], sc[ni][1]));
                mx1 = fmaxf(mx1, fmaxf(sc[ni][2], sc[ni][3]));
            }
            mx0 = fmaxf(mx0, __shfl_xor_sync(0xffffffffu, mx0, 1));
            mx0 = fmaxf(mx0, __shfl_xor_sync(0xffffffffu, mx0, 2));
            mx1 = fmaxf(mx1, __shfl_xor_sync(0xffffffffu, mx1, 1));
            mx1 = fmaxf(mx1, __shfl_xor_sync(0xffffffffu, mx1, 2));
            const float mn0 = fmaxf(m0, mx0), mn1 = fmaxf(m1, mx1);
            const float al0 = ex2(m0 - mn0), al1 = ex2(m1 - mn1);
            float s0 = 0.f, s1 = 0.f;
#pragma unroll
            for (int ni = 0; ni < 8; ni++) {
                sc[ni][0] = ex2(sc[ni][0] - mn0); s0 += sc[ni][0];
                sc[ni][1] = ex2(sc[ni][1] - mn0); s0 += sc[ni][1];
                sc[ni][2] = ex2(sc[ni][2] - mn1); s1 += sc[ni][2];
                sc[ni][3] = ex2(sc[ni][3] - mn1); s1 += sc[ni][3];
            }
            s0 += __shfl_xor_sync(0xffffffffu, s0, 1);
            s0 += __shfl_xor_sync(0xffffffffu, s0, 2);
            s1 += __shfl_xor_sync(0xffffffffu, s1, 1);
            s1 += __shfl_xor_sync(0xffffffffu, s1, 2);
            l0 = l0 * al0 + s0;  l1 = l1 * al1 + s1;
            m0 = mn0;            m1 = mn1;
#pragma unroll
            for (int ni = 0; ni < 8; ni++) {
                oc[ni][0] *= al0; oc[ni][1] *= al0;
                oc[ni][2] *= al1; oc[ni][3] *= al1;
            }

            // ---- O += P V: batch 4 V-ldsm per ks, then 8 MMAs ----
#pragma unroll
            for (int ks = 0; ks < 4; ks++) {
                uint32_t ph[4];
                ph[0] = pack_h2(sc[2*ks][0],   sc[2*ks][1]);
                ph[1] = pack_h2(sc[2*ks][2],   sc[2*ks][3]);
                ph[2] = pack_h2(sc[2*ks+1][0], sc[2*ks+1][1]);
                ph[3] = pack_h2(sc[2*ks+1][2], sc[2*ks+1][3]);
                const int keyr = ks*16 + t_row;
                uint32_t vF[4][4];
#pragma unroll
                for (int pp = 0; pp < 4; pp++) {
                    const uint32_t vo = (uint32_t)(keyr * KSTR + 16*pp + t_col) * 2;
                    ldsm_x4t(vF[pp][0], vF[pp][1], vF[pp][2], vF[pp][3], uV + vo);
                }
#pragma unroll
                for (int pp = 0; pp < 4; pp++) {
                    mma_f16(oc[2*pp],   ph, vF[pp][0], vF[pp][1]);
                    mma_f16(oc[2*pp+1], ph, vF[pp][2], vF[pp][3]);
                }
            }
        }
    }

    // ---- epilogue: normalize, pack fp16, write g_att [M,E] ----
    const float inv0 = 1.f / l0, inv1 = 1.f / l1;
    const int r0row = q0 + warp*16 + (lane >> 2);
#pragma unroll
    for (int ni = 0; ni < 8; ni++) {
        const int d = ni*8 + (lane & 3)*2;
        const size_t col = (size_t)h*DD + d;
        size_t idx = (((size_t)b*SS + r0row)*EE + col) >> 1;
        ((uint32_t*)g_att)[idx] = pack_h2(oc[ni][0]*inv0, oc[ni][1]*inv0);
        idx = (((size_t)b*SS + r0row + 8)*EE + col) >> 1;
        ((uint32_t*)g_att)[idx] = pack_h2(oc[ni][2]*inv1, oc[ni][3]*inv1);
    }
}

// ---------------------------------------------------------------------------
extern "C" void kernel_launch(void* const* d_in, const int* in_sizes, int n_in,
                              void* d_out, int out_size)
{
    const float* x  = (const float*)d_in[0];
    const float* Wq = (const float*)d_in[1];
    const float* bq = (const float*)d_in[2];
    const float* Wk = (const float*)d_in[3];
    const float* bk = (const float*)d_in[4];
    const float* Wv = (const float*)d_in[5];
    const float* bv = (const float*)d_in[6];
    const float* Wo = (const float*)d_in[7];
    const float* bo = (const float*)d_in[8];
    float* out = (float*)d_out;

    conv_fused<<<(1 << 21) / 256, 256>>>(x, Wq, Wk, Wv, Wo);

    const int gsmem = 3 * 2 * GS * 2;                 // 61,440 B (3 stages)
    const int asmem = (QTILE + 2 * 4 * ATILE) * 2;    // 92,160 B
    cudaFuncSetAttribute(gemm_qkv, cudaFuncAttributeMaxDynamicSharedMemorySize, gsmem);
    cudaFuncSetAttribute(gemm_out, cudaFuncAttributeMaxDynamicSharedMemorySize, gsmem);
    cudaFuncSetAttribute(attn_mma, cudaFuncAttributeMaxDynamicSharedMemorySize, asmem);

    gemm_qkv<<<dim3(MM/128, EE/128, 3), 256, gsmem>>>(bq, bk, bv);

    attn_mma<<<dim3(SS/128, BB*HH), 256, asmem>>>();

    gemm_out<<<dim3(MM/128, EE/128), 256, gsmem>>>(bo, out);
}